// round 1
// baseline (speedup 1.0000x reference)
#include <cuda_runtime.h>
#include <math.h>

// ---------------------------------------------------------------------------
// Problem constants
//   B=8, N=1024 (TOK=8192), D=768, NH=12 (dh=64), MLPH=3072,
//   DI=1536, DS=16, DTR=48, K=4
// ---------------------------------------------------------------------------

// Scratch (allocation-free: static __device__ arrays)
__device__ float g_ln   [8192u * 768u];        // LN output (reused 3x)
__device__ float g_qkv  [8192u * 2304u];       // fused QKV
__device__ float g_sc   [96u * 1024u * 1024u]; // attention scores (b*12+h, q, k)
__device__ float g_attn [8192u * 768u];        // attention output pre-proj
__device__ float g_h    [8192u * 3072u];       // MLP hidden / mamba xz
__device__ float g_u    [8192u * 1536u];       // conv+silu output
__device__ float g_dbl  [8192u * 80u];         // xproj output (dt_raw | B | C)
__device__ float g_dt   [8192u * 1536u];       // softplus dt
__device__ float g_y    [8192u * 1536u];       // scan output (pre out-proj)

__device__ __forceinline__ float gelu_exact(float v) {
    return 0.5f * v * (1.0f + erff(v * 0.7071067811865475f));
}
__device__ __forceinline__ float softplus_f(float v) {
    return fmaxf(v, 0.0f) + log1pf(expf(-fabsf(v)));
}
__device__ __forceinline__ float silu_f(float v) {
    return v / (1.0f + expf(-v));
}

// ---------------------------------------------------------------------------
// Generic tiled SGEMM: C[M,N] = epi( scale * A[M,K] @ op(B) )
//   TB=false: op(B)=B[K,N] (NN)   TB=true: op(B)=B[N,K]^T (NT)
//   Batched via blockIdx.z with two-level stride: z -> (zb = z/ZH, zh = z%ZH)
// EPI: 0 none, 1 +bias, 2 +bias+resid, 3 gelu(+bias), 4 softplus(+bias),
//      5 resid + sigmoid(gate)*acc
// Requirements: M%128==0, K%8==0, lda/ldb multiples of 4. N may be ragged.
// ---------------------------------------------------------------------------
template<bool TB, int EPI>
__global__ __launch_bounds__(256)
void gemm_kernel(const float* __restrict__ A, int lda, long long sAh, long long sAb,
                 const float* __restrict__ B, int ldb, long long sBh, long long sBb,
                 float* __restrict__ C, int ldc, long long sCh, long long sCb,
                 int M, int N, int K, int ZH,
                 const float* __restrict__ bias,
                 const float* __restrict__ resid, int ldr,
                 float scale, const float* __restrict__ gatep)
{
    __shared__ float As[8][128];
    __shared__ float Bs[8][128];

    int z  = blockIdx.z;
    int zh = z % ZH, zb = z / ZH;
    A += zh * sAh + (long long)zb * sAb;
    B += zh * sBh + (long long)zb * sBb;
    C += zh * sCh + (long long)zb * sCb;

    int m0 = blockIdx.y * 128;
    int n0 = blockIdx.x * 128;
    int tid = threadIdx.x;
    int tx = tid & 15, ty = tid >> 4;

    float acc[8][8];
    #pragma unroll
    for (int i = 0; i < 8; i++)
        #pragma unroll
        for (int j = 0; j < 8; j++) acc[i][j] = 0.0f;

    int arow = tid >> 1;          // 0..127
    int acol = (tid & 1) * 4;     // 0 or 4
    int bkrow = tid >> 5;         // 0..7   (NN path)
    int bncol = (tid & 31) * 4;   // 0..124 (NN path)

    for (int k0 = 0; k0 < K; k0 += 8) {
        // A tile -> As[k][m]
        {
            const float* ap = A + (long long)(m0 + arow) * lda + k0 + acol;
            float4 v = *(const float4*)ap;
            As[acol + 0][arow] = v.x;
            As[acol + 1][arow] = v.y;
            As[acol + 2][arow] = v.z;
            As[acol + 3][arow] = v.w;
        }
        if (TB) {
            // B[n,k] -> Bs[k][n]
            float4 v = make_float4(0.f, 0.f, 0.f, 0.f);
            if (n0 + arow < N)
                v = *(const float4*)(B + (long long)(n0 + arow) * ldb + k0 + acol);
            Bs[acol + 0][arow] = v.x;
            Bs[acol + 1][arow] = v.y;
            Bs[acol + 2][arow] = v.z;
            Bs[acol + 3][arow] = v.w;
        } else {
            // B[k,n] -> Bs[k][n]
            int n = n0 + bncol;
            const float* bp = B + (long long)(k0 + bkrow) * ldb + n;
            float4 v;
            if (n + 3 < N) {
                v = *(const float4*)bp;
            } else {
                v.x = (n + 0 < N) ? bp[0] : 0.f;
                v.y = (n + 1 < N) ? bp[1] : 0.f;
                v.z = (n + 2 < N) ? bp[2] : 0.f;
                v.w = (n + 3 < N) ? bp[3] : 0.f;
            }
            *(float4*)&Bs[bkrow][bncol] = v;
        }
        __syncthreads();
        #pragma unroll
        for (int kk = 0; kk < 8; kk++) {
            float a[8], b[8];
            *(float4*)&a[0] = *(const float4*)&As[kk][ty * 4];
            *(float4*)&a[4] = *(const float4*)&As[kk][64 + ty * 4];
            *(float4*)&b[0] = *(const float4*)&Bs[kk][tx * 4];
            *(float4*)&b[4] = *(const float4*)&Bs[kk][64 + tx * 4];
            #pragma unroll
            for (int i = 0; i < 8; i++)
                #pragma unroll
                for (int j = 0; j < 8; j++)
                    acc[i][j] = fmaf(a[i], b[j], acc[i][j]);
        }
        __syncthreads();
    }

    float gmul = 1.0f;
    if (EPI == 5) gmul = 1.0f / (1.0f + expf(-gatep[0]));

    #pragma unroll
    for (int i = 0; i < 8; i++) {
        int m = m0 + ((i < 4) ? (ty * 4 + i) : (64 + ty * 4 + i - 4));
        #pragma unroll
        for (int j = 0; j < 8; j++) {
            int n = n0 + ((j < 4) ? (tx * 4 + j) : (64 + tx * 4 + j - 4));
            if (n >= N) continue;
            float v = acc[i][j] * scale;
            if (EPI >= 1 && EPI <= 4) v += bias[n];
            if (EPI == 3) v = gelu_exact(v);
            if (EPI == 4) v = softplus_f(v);
            if (EPI == 2) v += resid[(long long)m * ldr + n];
            if (EPI == 5) v = resid[(long long)m * ldr + n] + gmul * v;
            C[(long long)m * ldc + n] = v;
        }
    }
}

// ---------------------------------------------------------------------------
// LayerNorm over rows of 768. One block per row, 256 threads x 3 elements.
// ---------------------------------------------------------------------------
__global__ __launch_bounds__(256)
void ln_kernel(const float* __restrict__ x, const float* __restrict__ g,
               const float* __restrict__ b, float* __restrict__ y)
{
    long long row = blockIdx.x;
    const float* xr = x + row * 768;
    float* yr = y + row * 768;
    int tid = threadIdx.x;

    float v0 = xr[tid], v1 = xr[tid + 256], v2 = xr[tid + 512];
    float s  = v0 + v1 + v2;
    float ss = v0 * v0 + v1 * v1 + v2 * v2;

    #pragma unroll
    for (int o = 16; o; o >>= 1) {
        s  += __shfl_xor_sync(0xffffffffu, s, o);
        ss += __shfl_xor_sync(0xffffffffu, ss, o);
    }
    __shared__ float sh_s[8], sh_ss[8];
    int w = tid >> 5, l = tid & 31;
    if (l == 0) { sh_s[w] = s; sh_ss[w] = ss; }
    __syncthreads();
    if (w == 0) {
        float s2  = (l < 8) ? sh_s[l]  : 0.f;
        float ss2 = (l < 8) ? sh_ss[l] : 0.f;
        #pragma unroll
        for (int o = 4; o; o >>= 1) {
            s2  += __shfl_xor_sync(0xffffffffu, s2, o);
            ss2 += __shfl_xor_sync(0xffffffffu, ss2, o);
        }
        if (l == 0) { sh_s[0] = s2; sh_ss[0] = ss2; }
    }
    __syncthreads();
    float mean = sh_s[0] * (1.0f / 768.0f);
    float var  = sh_ss[0] * (1.0f / 768.0f) - mean * mean;
    float rstd = rsqrtf(var + 1e-5f);

    yr[tid]       = (v0 - mean) * rstd * g[tid]       + b[tid];
    yr[tid + 256] = (v1 - mean) * rstd * g[tid + 256] + b[tid + 256];
    yr[tid + 512] = (v2 - mean) * rstd * g[tid + 512] + b[tid + 512];
}

// ---------------------------------------------------------------------------
// Row softmax over 1024 columns. One block per row, 256 threads x float4.
// ---------------------------------------------------------------------------
__global__ __launch_bounds__(256)
void softmax_kernel(float* __restrict__ S)
{
    long long row = blockIdx.x;
    float4* p = reinterpret_cast<float4*>(S + row * 1024);
    int tid = threadIdx.x;
    float4 v = p[tid];

    float mx = fmaxf(fmaxf(v.x, v.y), fmaxf(v.z, v.w));
    __shared__ float shm[8];
    #pragma unroll
    for (int o = 16; o; o >>= 1) mx = fmaxf(mx, __shfl_xor_sync(0xffffffffu, mx, o));
    int w = tid >> 5, l = tid & 31;
    if (l == 0) shm[w] = mx;
    __syncthreads();
    if (w == 0) {
        float m2 = (l < 8) ? shm[l] : -1e30f;
        #pragma unroll
        for (int o = 4; o; o >>= 1) m2 = fmaxf(m2, __shfl_xor_sync(0xffffffffu, m2, o));
        if (l == 0) shm[0] = m2;
    }
    __syncthreads();
    float m = shm[0];

    v.x = expf(v.x - m); v.y = expf(v.y - m);
    v.z = expf(v.z - m); v.w = expf(v.w - m);
    float s = v.x + v.y + v.z + v.w;
    __shared__ float shs[8];
    #pragma unroll
    for (int o = 16; o; o >>= 1) s += __shfl_xor_sync(0xffffffffu, s, o);
    if (l == 0) shs[w] = s;
    __syncthreads();
    if (w == 0) {
        float s2 = (l < 8) ? shs[l] : 0.f;
        #pragma unroll
        for (int o = 4; o; o >>= 1) s2 += __shfl_xor_sync(0xffffffffu, s2, o);
        if (l == 0) shs[0] = s2;
    }
    __syncthreads();
    float inv = 1.0f / shs[0];
    v.x *= inv; v.y *= inv; v.z *= inv; v.w *= inv;
    p[tid] = v;
}

// ---------------------------------------------------------------------------
// Depthwise causal conv (K=4) + bias + SiLU.  u channel d = xz column d.
// ---------------------------------------------------------------------------
__global__ __launch_bounds__(256)
void conv_silu_kernel(const float* __restrict__ xz, const float* __restrict__ cw,
                      const float* __restrict__ cb, float* __restrict__ u)
{
    int idx = blockIdx.x * 256 + threadIdx.x;   // < 8192*1536
    int d   = idx % 1536;
    int tok = idx / 1536;
    int t   = tok & 1023;
    float acc = cb[d];
    const float* base = xz + (long long)tok * 3072 + d;
    #pragma unroll
    for (int j = 0; j < 4; j++) {
        int tt = t - 3 + j;
        if (tt >= 0) acc = fmaf(base[(long long)(j - 3) * 3072], cw[d * 4 + j], acc);
    }
    u[(long long)tok * 1536 + d] = silu_f(acc);
}

// ---------------------------------------------------------------------------
// Selective scan. 16 lanes per (b,d): lane s owns state s (independent scalar
// recurrence), width-16 shfl reduction gives y each step.
// Fused: y = (scan + u*D) * silu(res)
// ---------------------------------------------------------------------------
__global__ __launch_bounds__(256)
void scan_kernel(const float* __restrict__ dt, const float* __restrict__ dbl,
                 const float* __restrict__ u, const float* __restrict__ xz,
                 const float* __restrict__ Alog, const float* __restrict__ Dp,
                 float* __restrict__ y)
{
    int gg = blockIdx.x * 16 + (threadIdx.x >> 4);  // (b,d) group
    int s  = threadIdx.x & 15;
    int d  = gg % 1536, b = gg / 1536;

    float A  = -expf(Alog[d * 16 + s]);
    float Dv = Dp[d];
    float h  = 0.0f;
    long long tokbase = (long long)b * 1024;

    for (int t = 0; t < 1024; t++) {
        long long tok = tokbase + t;
        float dtv = dt[tok * 1536 + d];
        float uv  = u [tok * 1536 + d];
        float Bv  = dbl[tok * 80 + 48 + s];
        float Cv  = dbl[tok * 80 + 64 + s];
        float dA  = expf(dtv * A);
        h = fmaf(dA, h, dtv * Bv * uv);
        float part = h * Cv;
        part += __shfl_xor_sync(0xffffffffu, part, 8, 16);
        part += __shfl_xor_sync(0xffffffffu, part, 4, 16);
        part += __shfl_xor_sync(0xffffffffu, part, 2, 16);
        part += __shfl_xor_sync(0xffffffffu, part, 1, 16);
        if (s == 0) {
            float rv = xz[tok * 3072 + 1536 + d];
            y[tok * 1536 + d] = (part + uv * Dv) * silu_f(rv);
        }
    }
}

// ---------------------------------------------------------------------------
// Host orchestration
// ---------------------------------------------------------------------------
extern "C" void kernel_launch(void* const* d_in, const int* in_sizes, int n_in,
                              void* d_out, int out_size)
{
    const float* x    = (const float*)d_in[0];
    const float* n1g  = (const float*)d_in[1];
    const float* n1b  = (const float*)d_in[2];
    const float* aiw  = (const float*)d_in[3];
    const float* aib  = (const float*)d_in[4];
    const float* aow  = (const float*)d_in[5];
    const float* aob  = (const float*)d_in[6];
    const float* n2g  = (const float*)d_in[7];
    const float* n2b  = (const float*)d_in[8];
    const float* w1   = (const float*)d_in[9];
    const float* b1   = (const float*)d_in[10];
    const float* w2   = (const float*)d_in[11];
    const float* b2   = (const float*)d_in[12];
    const float* n3g  = (const float*)d_in[13];
    const float* n3b  = (const float*)d_in[14];
    const float* minw = (const float*)d_in[15];
    const float* cw   = (const float*)d_in[16];
    const float* cb   = (const float*)d_in[17];
    const float* xpw  = (const float*)d_in[18];
    const float* dtw  = (const float*)d_in[19];
    const float* dtbi = (const float*)d_in[20];
    const float* alog = (const float*)d_in[21];
    const float* dpar = (const float*)d_in[22];
    const float* mow  = (const float*)d_in[23];
    const float* gate = (const float*)d_in[24];
    float* out = (float*)d_out;

    float *ln, *qkv, *sc, *attn, *hb, *ub, *dbl, *gdt, *yb;
    cudaGetSymbolAddress((void**)&ln,   g_ln);
    cudaGetSymbolAddress((void**)&qkv,  g_qkv);
    cudaGetSymbolAddress((void**)&sc,   g_sc);
    cudaGetSymbolAddress((void**)&attn, g_attn);
    cudaGetSymbolAddress((void**)&hb,   g_h);
    cudaGetSymbolAddress((void**)&ub,   g_u);
    cudaGetSymbolAddress((void**)&dbl,  g_dbl);
    cudaGetSymbolAddress((void**)&gdt,  g_dt);
    cudaGetSymbolAddress((void**)&yb,   g_y);

    const long long TQ = 1024LL * 2304LL;   // per-batch qkv stride

    // 1) LN1(x)
    ln_kernel<<<8192, 256>>>(x, n1g, n1b, ln);

    // 2) QKV = LN1 @ attn_in_w^T + b  (NT, M=8192 N=2304 K=768)
    gemm_kernel<true, 1><<<dim3(18, 64, 1), 256>>>(
        ln, 768, 0, 0, aiw, 768, 0, 0, qkv, 2304, 0, 0,
        8192, 2304, 768, 1, aib, nullptr, 0, 1.0f, nullptr);

    // 3) scores = Q @ K^T / 8  (NT batched 96, M=N=1024 K=64)
    gemm_kernel<true, 0><<<dim3(8, 8, 96), 256>>>(
        qkv,       2304, 64, TQ,
        qkv + 768, 2304, 64, TQ,
        sc, 1024, 1024LL * 1024LL, 12LL * 1024LL * 1024LL,
        1024, 1024, 64, 12, nullptr, nullptr, 0, 0.125f, nullptr);

    // 4) softmax rows
    softmax_kernel<<<96 * 1024, 256>>>(sc);

    // 5) O = P @ V  (NN batched 96, M=1024 N=64 K=1024)
    gemm_kernel<false, 0><<<dim3(1, 8, 96), 256>>>(
        sc, 1024, 1024LL * 1024LL, 12LL * 1024LL * 1024LL,
        qkv + 1536, 2304, 64, TQ,
        attn, 768, 64, 1024LL * 768LL,
        1024, 64, 1024, 12, nullptr, nullptr, 0, 1.0f, nullptr);

    // 6) x = x_in + O @ attn_out_w^T + b  (NT, writes residual stream to out)
    gemm_kernel<true, 2><<<dim3(6, 64, 1), 256>>>(
        attn, 768, 0, 0, aow, 768, 0, 0, out, 768, 0, 0,
        8192, 768, 768, 1, aob, x, 768, 1.0f, nullptr);

    // 7) LN2
    ln_kernel<<<8192, 256>>>(out, n2g, n2b, ln);

    // 8) H = gelu(LN2 @ W1 + b1)  (NN, N=3072)
    gemm_kernel<false, 3><<<dim3(24, 64, 1), 256>>>(
        ln, 768, 0, 0, w1, 3072, 0, 0, hb, 3072, 0, 0,
        8192, 3072, 768, 1, b1, nullptr, 0, 1.0f, nullptr);

    // 9) x += H @ W2 + b2  (NN)
    gemm_kernel<false, 2><<<dim3(6, 64, 1), 256>>>(
        hb, 3072, 0, 0, w2, 768, 0, 0, out, 768, 0, 0,
        8192, 768, 3072, 1, b2, out, 768, 1.0f, nullptr);

    // 10) LN3
    ln_kernel<<<8192, 256>>>(out, n3g, n3b, ln);

    // 11) xz = LN3 @ m_in_w  (NN, N=3072)
    gemm_kernel<false, 0><<<dim3(24, 64, 1), 256>>>(
        ln, 768, 0, 0, minw, 3072, 0, 0, hb, 3072, 0, 0,
        8192, 3072, 768, 1, nullptr, nullptr, 0, 1.0f, nullptr);

    // 12) u = silu(causal depthwise conv(xz[:, :1536]) + cb)
    conv_silu_kernel<<<49152, 256>>>(hb, cw, cb, ub);

    // 13) dbl = u @ xproj_w  (NN, N=80)
    gemm_kernel<false, 0><<<dim3(1, 64, 1), 256>>>(
        ub, 1536, 0, 0, xpw, 80, 0, 0, dbl, 80, 0, 0,
        8192, 80, 1536, 1, nullptr, nullptr, 0, 1.0f, nullptr);

    // 14) dt = softplus(dbl[:, :48] @ dt_w + dt_b)  (NN, K=48)
    gemm_kernel<false, 4><<<dim3(12, 64, 1), 256>>>(
        dbl, 80, 0, 0, dtw, 1536, 0, 0, gdt, 1536, 0, 0,
        8192, 1536, 48, 1, dtbi, nullptr, 0, 1.0f, nullptr);

    // 15) selective scan + (u*D) + *silu(res)
    scan_kernel<<<768, 256>>>(gdt, dbl, ub, hb, alog, dpar, yb);

    // 16) out = x + sigmoid(gate) * (y @ m_out_w)  (NN)
    gemm_kernel<false, 5><<<dim3(6, 64, 1), 256>>>(
        yb, 1536, 0, 0, mow, 768, 0, 0, out, 768, 0, 0,
        8192, 768, 1536, 1, nullptr, out, 768, 1.0f, gate);
}

// round 3
// speedup vs baseline: 1.1886x; 1.1886x over previous
#include <cuda_runtime.h>
#include <mma.h>
#include <cstdint>
#include <math.h>

using namespace nvcuda;

// ---------------------------------------------------------------------------
// MambaViTBlock: B=8, N=1024 (TOK=8192), D=768, NH=12 (dh=64), MLPH=3072,
//                DI=1536, DS=16, DTR=48, K=4
// Round 3: GEMMs on WMMA tf32 (m16n16k8) + cp.async double buffering.
// (tcgen05 unavailable: harness PTX target is compute_103 without 'a'.)
// ---------------------------------------------------------------------------

// Scratch (allocation-free: static __device__ arrays)
__device__ float g_ln   [8192u * 768u];        // LN output (reused 3x)
__device__ float g_qkv  [8192u * 2304u];       // fused QKV
__device__ float g_sc   [96u * 1024u * 1024u]; // attention scores
__device__ float g_attn [8192u * 768u];        // attention out pre-proj
__device__ float g_h    [8192u * 3072u];       // MLP hidden / mamba xz
__device__ float g_u    [8192u * 1536u];       // conv+silu output
__device__ float g_dbl  [8192u * 80u];         // xproj output (dt_raw | B | C)
__device__ float g_dt   [8192u * 1536u];       // softplus dt
__device__ float g_y    [8192u * 1536u];       // scan output
__device__ float g_wt   [8454144u];            // transposed weights
__device__ float g_vt   [96u * 64u * 1024u];   // transposed V per head

// offsets into g_wt (floats)
#define WT_W1   0LL
#define WT_W2   2359296LL
#define WT_MIN  4718592LL
#define WT_MOW  7077888LL
#define WT_XPW  8257536LL
#define WT_DTW  8380416LL

__device__ __forceinline__ float gelu_exact(float v) {
    return 0.5f * v * (1.0f + erff(v * 0.7071067811865475f));
}
__device__ __forceinline__ float softplus_f(float v) {
    return fmaxf(v, 0.0f) + log1pf(expf(-fabsf(v)));
}
__device__ __forceinline__ float silu_f(float v) {
    return v / (1.0f + expf(-v));
}

__device__ __forceinline__ uint32_t smem_u32(const void* p) {
    uint32_t a;
    asm("{ .reg .u64 t; cvta.to.shared.u64 t, %1; cvt.u32.u64 %0, t; }" : "=r"(a) : "l"(p));
    return a;
}
__device__ __forceinline__ void cp_async16(uint32_t dst, const void* src, int sz) {
    asm volatile("cp.async.ca.shared.global [%0], [%1], 16, %2;"
                 :: "r"(dst), "l"(src), "r"(sz));
}
__device__ __forceinline__ void cp_commit() {
    asm volatile("cp.async.commit_group;");
}
template<int N>
__device__ __forceinline__ void cp_wait() {
    asm volatile("cp.async.wait_group %0;" :: "n"(N));
}

// ---------------------------------------------------------------------------
// WMMA tf32 GEMM:  C[M,N] = epi( scale * A[M,K] @ B[N,K]^T )
//   A row-major [M,K]; B row-major [N,K] (i.e. K-major — NT gemm).
//   Tile: 128x128, BK=16. 256 threads = 8 warps (4 M-warps x 2 N-warps),
//   warp tile 32x64 = 2x4 wmma m16n16k8 accumulators.
//   Requirements: M % 128 == 0, K % 16 == 0, N % 16 == 0 (N ragged by tile).
//   Batched via blockIdx.z -> (zh = z % ZH, zb = z / ZH).
// EPI: 0 none, 1 +bias, 2 +bias+resid, 3 gelu(+bias), 4 softplus(+bias),
//      5 resid + sigmoid(gate)*acc
// ---------------------------------------------------------------------------
#define TLD 20   // smem row stride in floats (80B: 16B-aligned, conflict-free)

template<int EPI>
__global__ __launch_bounds__(256)
void tgemm(const float* __restrict__ A, int lda, long long sAh, long long sAb,
           const float* __restrict__ B, int ldb, long long sBh, long long sBb,
           float* __restrict__ C, int ldc, long long sCh, long long sCb,
           int M, int N, int K, int ZH,
           const float* __restrict__ bias,
           const float* __restrict__ resid, int ldr,
           float scale, const float* __restrict__ gatep)
{
    __shared__ float sm[4 * 128 * TLD];   // A0 | B0 | A1 | B1
    const uint32_t sb = smem_u32(sm);

    const int tid = threadIdx.x;
    const int wid = tid >> 5, lid = tid & 31;
    const int warpM = wid & 3;            // 0..3 -> 32-row slice
    const int warpN = wid >> 2;           // 0..1 -> 64-col slice

    const int z = blockIdx.z, zh = z % ZH, zb = z / ZH;
    A += zh * sAh + (long long)zb * sAb;
    B += zh * sBh + (long long)zb * sBb;
    C += zh * sCh + (long long)zb * sCb;
    const int m0 = blockIdx.y * 128, n0 = blockIdx.x * 128;

    const int NC = K / 16;

    wmma::fragment<wmma::accumulator, 16, 16, 8, float> acc[2][4];
    #pragma unroll
    for (int i = 0; i < 2; i++)
        #pragma unroll
        for (int j = 0; j < 4; j++) wmma::fill_fragment(acc[i][j], 0.0f);

    // stage loader: 512 float4 chunks per operand, 2 per thread
    const int r0a = tid >> 1;             // rows handled by this thread
    const int c4a = (tid & 1) * 2;        // chunk pair start (0 or 2)

    auto stage = [&](int c, int buf) {
        const int k0 = c * 16;
        const uint32_t offA = (uint32_t)buf * (2 * 128 * TLD) * 4;
        const uint32_t offB = offA + (128 * TLD) * 4;
        #pragma unroll
        for (int q = 0; q < 2; q++) {
            const int row = r0a;
            const int c4  = c4a + q;
            uint32_t da = sb + offA + (uint32_t)(row * TLD + c4 * 4) * 4;
            cp_async16(da, A + (long long)(m0 + row) * lda + k0 + c4 * 4, 16);
            uint32_t db = sb + offB + (uint32_t)(row * TLD + c4 * 4) * 4;
            const bool bv = (n0 + row) < N;
            const float* bsrc = bv ? (B + (long long)(n0 + row) * ldb + k0 + c4 * 4) : B;
            cp_async16(db, bsrc, bv ? 16 : 0);
        }
    };

    auto compute = [&](int buf) {
        const float* Asb = sm + buf * (2 * 128 * TLD);
        const float* Bsb = Asb + 128 * TLD;
        #pragma unroll
        for (int kk = 0; kk < 16; kk += 8) {
            wmma::fragment<wmma::matrix_a, 16, 16, 8, wmma::precision::tf32, wmma::row_major> af[2];
            wmma::fragment<wmma::matrix_b, 16, 16, 8, wmma::precision::tf32, wmma::col_major> bf[4];
            #pragma unroll
            for (int i = 0; i < 2; i++) {
                wmma::load_matrix_sync(af[i], Asb + (warpM * 32 + i * 16) * TLD + kk, TLD);
                #pragma unroll
                for (int e = 0; e < af[i].num_elements; e++)
                    af[i].x[e] = wmma::__float_to_tf32(af[i].x[e]);
            }
            #pragma unroll
            for (int j = 0; j < 4; j++) {
                wmma::load_matrix_sync(bf[j], Bsb + (warpN * 64 + j * 16) * TLD + kk, TLD);
                #pragma unroll
                for (int e = 0; e < bf[j].num_elements; e++)
                    bf[j].x[e] = wmma::__float_to_tf32(bf[j].x[e]);
            }
            #pragma unroll
            for (int i = 0; i < 2; i++)
                #pragma unroll
                for (int j = 0; j < 4; j++)
                    wmma::mma_sync(acc[i][j], af[i], bf[j], acc[i][j]);
        }
    };

    stage(0, 0);
    cp_commit();

    for (int c = 0; c < NC; c++) {
        if (c + 1 < NC) {
            stage(c + 1, (c + 1) & 1);
            cp_commit();
            cp_wait<1>();
        } else {
            cp_wait<0>();
        }
        __syncthreads();
        compute(c & 1);
        __syncthreads();
    }

    // ---------------- epilogue (reuse smem as per-warp 16x16 patches) -------
    float gmul = 1.0f;
    if (EPI == 5) gmul = 1.0f / (1.0f + expf(-gatep[0]));
    float* patch = sm + wid * 256;

    #pragma unroll
    for (int i = 0; i < 2; i++) {
        #pragma unroll
        for (int j = 0; j < 4; j++) {
            const int nfrag = n0 + warpN * 64 + j * 16;
            if (nfrag >= N) continue;
            wmma::store_matrix_sync(patch, acc[i][j], 16, wmma::mem_row_major);
            __syncwarp();
            const int mbase = m0 + warpM * 32 + i * 16;
            #pragma unroll
            for (int q = 0; q < 2; q++) {
                const int idx = lid + 32 * q;       // 0..63
                const int r  = idx >> 2, c4 = idx & 3;
                float4 v4 = *(const float4*)(patch + r * 16 + c4 * 4);
                const int n = nfrag + c4 * 4;
                const int m = mbase + r;
                float vv[4] = {v4.x, v4.y, v4.z, v4.w};
                #pragma unroll
                for (int qq = 0; qq < 4; qq++) {
                    float t = vv[qq] * scale;
                    if (EPI >= 1 && EPI <= 4) t += bias[n + qq];
                    if (EPI == 3) t = gelu_exact(t);
                    if (EPI == 4) t = softplus_f(t);
                    if (EPI == 2) t += resid[(long long)m * ldr + n + qq];
                    if (EPI == 5) t = resid[(long long)m * ldr + n + qq] + gmul * t;
                    vv[qq] = t;
                }
                *(float4*)(C + (long long)m * ldc + n) = make_float4(vv[0], vv[1], vv[2], vv[3]);
            }
            __syncwarp();
        }
    }
}

// ---------------------------------------------------------------------------
// Tiled transpose: out[c, r] = in[r, c].  Batched via z -> (zh, zb).
// ---------------------------------------------------------------------------
__global__ __launch_bounds__(256)
void transpose_kernel(const float* __restrict__ in, int ldi, long long sIh, long long sIb,
                      float* __restrict__ out, int ldo, long long sOh, long long sOb,
                      int R, int C, int ZH)
{
    __shared__ float t[32][33];
    const int z = blockIdx.z, zh = z % ZH, zb = z / ZH;
    in  += zh * sIh + (long long)zb * sIb;
    out += zh * sOh + (long long)zb * sOb;
    const int r0 = blockIdx.y * 32, c0 = blockIdx.x * 32;
    const int tx = threadIdx.x & 31, ty = threadIdx.x >> 5;
    #pragma unroll
    for (int i = 0; i < 32; i += 8) {
        const int r = r0 + ty + i, c = c0 + tx;
        t[ty + i][tx] = (r < R && c < C) ? in[(long long)r * ldi + c] : 0.f;
    }
    __syncthreads();
    #pragma unroll
    for (int i = 0; i < 32; i += 8) {
        const int r = c0 + ty + i, c = r0 + tx;
        if (r < C && c < R) out[(long long)r * ldo + c] = t[tx][ty + i];
    }
}

// ---------------------------------------------------------------------------
// LayerNorm over rows of 768
// ---------------------------------------------------------------------------
__global__ __launch_bounds__(256)
void ln_kernel(const float* __restrict__ x, const float* __restrict__ g,
               const float* __restrict__ b, float* __restrict__ y)
{
    long long row = blockIdx.x;
    const float* xr = x + row * 768;
    float* yr = y + row * 768;
    int tid = threadIdx.x;

    float v0 = xr[tid], v1 = xr[tid + 256], v2 = xr[tid + 512];
    float s  = v0 + v1 + v2;
    float ss = v0 * v0 + v1 * v1 + v2 * v2;

    #pragma unroll
    for (int o = 16; o; o >>= 1) {
        s  += __shfl_xor_sync(0xffffffffu, s, o);
        ss += __shfl_xor_sync(0xffffffffu, ss, o);
    }
    __shared__ float sh_s[8], sh_ss[8];
    int w = tid >> 5, l = tid & 31;
    if (l == 0) { sh_s[w] = s; sh_ss[w] = ss; }
    __syncthreads();
    if (w == 0) {
        float s2  = (l < 8) ? sh_s[l]  : 0.f;
        float ss2 = (l < 8) ? sh_ss[l] : 0.f;
        #pragma unroll
        for (int o = 4; o; o >>= 1) {
            s2  += __shfl_xor_sync(0xffffffffu, s2, o);
            ss2 += __shfl_xor_sync(0xffffffffu, ss2, o);
        }
        if (l == 0) { sh_s[0] = s2; sh_ss[0] = ss2; }
    }
    __syncthreads();
    float mean = sh_s[0] * (1.0f / 768.0f);
    float var  = sh_ss[0] * (1.0f / 768.0f) - mean * mean;
    float rstd = rsqrtf(var + 1e-5f);

    yr[tid]       = (v0 - mean) * rstd * g[tid]       + b[tid];
    yr[tid + 256] = (v1 - mean) * rstd * g[tid + 256] + b[tid + 256];
    yr[tid + 512] = (v2 - mean) * rstd * g[tid + 512] + b[tid + 512];
}

// ---------------------------------------------------------------------------
// Row softmax over 1024 columns
// ---------------------------------------------------------------------------
__global__ __launch_bounds__(256)
void softmax_kernel(float* __restrict__ S)
{
    long long row = blockIdx.x;
    float4* p = reinterpret_cast<float4*>(S + row * 1024);
    int tid = threadIdx.x;
    float4 v = p[tid];

    float mx = fmaxf(fmaxf(v.x, v.y), fmaxf(v.z, v.w));
    __shared__ float shm[8];
    #pragma unroll
    for (int o = 16; o; o >>= 1) mx = fmaxf(mx, __shfl_xor_sync(0xffffffffu, mx, o));
    int w = tid >> 5, l = tid & 31;
    if (l == 0) shm[w] = mx;
    __syncthreads();
    if (w == 0) {
        float m2 = (l < 8) ? shm[l] : -1e30f;
        #pragma unroll
        for (int o = 4; o; o >>= 1) m2 = fmaxf(m2, __shfl_xor_sync(0xffffffffu, m2, o));
        if (l == 0) shm[0] = m2;
    }
    __syncthreads();
    float m = shm[0];

    v.x = expf(v.x - m); v.y = expf(v.y - m);
    v.z = expf(v.z - m); v.w = expf(v.w - m);
    float s = v.x + v.y + v.z + v.w;
    __shared__ float shs[8];
    #pragma unroll
    for (int o = 16; o; o >>= 1) s += __shfl_xor_sync(0xffffffffu, s, o);
    if (l == 0) shs[w] = s;
    __syncthreads();
    if (w == 0) {
        float s2 = (l < 8) ? shs[l] : 0.f;
        #pragma unroll
        for (int o = 4; o; o >>= 1) s2 += __shfl_xor_sync(0xffffffffu, s2, o);
        if (l == 0) shs[0] = s2;
    }
    __syncthreads();
    float inv = 1.0f / shs[0];
    v.x *= inv; v.y *= inv; v.z *= inv; v.w *= inv;
    p[tid] = v;
}

// ---------------------------------------------------------------------------
// Depthwise causal conv (K=4) + bias + SiLU
// ---------------------------------------------------------------------------
__global__ __launch_bounds__(256)
void conv_silu_kernel(const float* __restrict__ xz, const float* __restrict__ cw,
                      const float* __restrict__ cb, float* __restrict__ u)
{
    int idx = blockIdx.x * 256 + threadIdx.x;   // < 8192*1536
    int d   = idx % 1536;
    int tok = idx / 1536;
    int t   = tok & 1023;
    float acc = cb[d];
    const float* base = xz + (long long)tok * 3072 + d;
    #pragma unroll
    for (int j = 0; j < 4; j++) {
        int tt = t - 3 + j;
        if (tt >= 0) acc = fmaf(base[(long long)(j - 3) * 3072], cw[d * 4 + j], acc);
    }
    u[(long long)tok * 1536 + d] = silu_f(acc);
}

// ---------------------------------------------------------------------------
// Selective scan: 16 lanes per (b,d) channel; fused +u*D and *silu(res)
// ---------------------------------------------------------------------------
__global__ __launch_bounds__(256)
void scan_kernel(const float* __restrict__ dt, const float* __restrict__ dbl,
                 const float* __restrict__ u, const float* __restrict__ xz,
                 const float* __restrict__ Alog, const float* __restrict__ Dp,
                 float* __restrict__ y)
{
    int gg = blockIdx.x * 16 + (threadIdx.x >> 4);  // (b,d) group
    int s  = threadIdx.x & 15;
    int d  = gg % 1536, b = gg / 1536;

    float A  = -expf(Alog[d * 16 + s]);
    float Dv = Dp[d];
    float h  = 0.0f;
    long long tokbase = (long long)b * 1024;

    for (int t = 0; t < 1024; t++) {
        long long tok = tokbase + t;
        float dtv = dt[tok * 1536 + d];
        float uv  = u [tok * 1536 + d];
        float Bv  = dbl[tok * 80 + 48 + s];
        float Cv  = dbl[tok * 80 + 64 + s];
        float dA  = expf(dtv * A);
        h = fmaf(dA, h, dtv * Bv * uv);
        float part = h * Cv;
        part += __shfl_xor_sync(0xffffffffu, part, 8, 16);
        part += __shfl_xor_sync(0xffffffffu, part, 4, 16);
        part += __shfl_xor_sync(0xffffffffu, part, 2, 16);
        part += __shfl_xor_sync(0xffffffffu, part, 1, 16);
        if (s == 0) {
            float rv = xz[tok * 3072 + 1536 + d];
            y[tok * 1536 + d] = (part + uv * Dv) * silu_f(rv);
        }
    }
}

// ---------------------------------------------------------------------------
// Host orchestration
// ---------------------------------------------------------------------------
extern "C" void kernel_launch(void* const* d_in, const int* in_sizes, int n_in,
                              void* d_out, int out_size)
{
    const float* x    = (const float*)d_in[0];
    const float* n1g  = (const float*)d_in[1];
    const float* n1b  = (const float*)d_in[2];
    const float* aiw  = (const float*)d_in[3];
    const float* aib  = (const float*)d_in[4];
    const float* aow  = (const float*)d_in[5];
    const float* aob  = (const float*)d_in[6];
    const float* n2g  = (const float*)d_in[7];
    const float* n2b  = (const float*)d_in[8];
    const float* w1   = (const float*)d_in[9];
    const float* b1   = (const float*)d_in[10];
    const float* w2   = (const float*)d_in[11];
    const float* b2   = (const float*)d_in[12];
    const float* n3g  = (const float*)d_in[13];
    const float* n3b  = (const float*)d_in[14];
    const float* minw = (const float*)d_in[15];
    const float* cw   = (const float*)d_in[16];
    const float* cb   = (const float*)d_in[17];
    const float* xpw  = (const float*)d_in[18];
    const float* dtw  = (const float*)d_in[19];
    const float* dtbi = (const float*)d_in[20];
    const float* alog = (const float*)d_in[21];
    const float* dpar = (const float*)d_in[22];
    const float* mow  = (const float*)d_in[23];
    const float* gate = (const float*)d_in[24];
    float* out = (float*)d_out;

    float *ln, *qkv, *sc, *attn, *hb, *ub, *dbl, *gdt, *yb, *wt, *vt;
    cudaGetSymbolAddress((void**)&ln,   g_ln);
    cudaGetSymbolAddress((void**)&qkv,  g_qkv);
    cudaGetSymbolAddress((void**)&sc,   g_sc);
    cudaGetSymbolAddress((void**)&attn, g_attn);
    cudaGetSymbolAddress((void**)&hb,   g_h);
    cudaGetSymbolAddress((void**)&ub,   g_u);
    cudaGetSymbolAddress((void**)&dbl,  g_dbl);
    cudaGetSymbolAddress((void**)&gdt,  g_dt);
    cudaGetSymbolAddress((void**)&yb,   g_y);
    cudaGetSymbolAddress((void**)&wt,   g_wt);
    cudaGetSymbolAddress((void**)&vt,   g_vt);

    const long long TQ = 1024LL * 2304LL;   // per-batch qkv stride

    // 0) one-shot weight transposes (NN -> NT form)
    transpose_kernel<<<dim3(96, 24, 1), 256>>>(w1, 3072, 0, 0, wt + WT_W1, 768, 0, 0, 768, 3072, 1);
    transpose_kernel<<<dim3(24, 96, 1), 256>>>(w2, 768, 0, 0, wt + WT_W2, 3072, 0, 0, 3072, 768, 1);
    transpose_kernel<<<dim3(96, 24, 1), 256>>>(minw, 3072, 0, 0, wt + WT_MIN, 768, 0, 0, 768, 3072, 1);
    transpose_kernel<<<dim3(24, 48, 1), 256>>>(mow, 768, 0, 0, wt + WT_MOW, 1536, 0, 0, 1536, 768, 1);
    transpose_kernel<<<dim3(3, 48, 1), 256>>>(xpw, 80, 0, 0, wt + WT_XPW, 1536, 0, 0, 1536, 80, 1);
    transpose_kernel<<<dim3(48, 2, 1), 256>>>(dtw, 1536, 0, 0, wt + WT_DTW, 48, 0, 0, 48, 1536, 1);

    // 1) LN1(x)
    ln_kernel<<<8192, 256>>>(x, n1g, n1b, ln);

    // 2) QKV = LN1 @ attn_in_w^T + b   (M=8192, N=2304, K=768)
    tgemm<1><<<dim3(18, 64, 1), 256>>>(
        ln, 768, 0, 0, aiw, 768, 0, 0, qkv, 2304, 0, 0,
        8192, 2304, 768, 1, aib, nullptr, 0, 1.0f, nullptr);

    // 3) scores = Q @ K^T / 8   (96 heads, M=N=1024, K=64)
    tgemm<0><<<dim3(8, 8, 96), 256>>>(
        qkv,       2304, 64, TQ,
        qkv + 768, 2304, 64, TQ,
        sc, 1024, 1024LL * 1024LL, 12LL * 1024LL * 1024LL,
        1024, 1024, 64, 12, nullptr, nullptr, 0, 0.125f, nullptr);

    // 4) softmax rows
    softmax_kernel<<<96 * 1024, 256>>>(sc);

    // 5) V^T per head: [1024,64] -> [64,1024]
    transpose_kernel<<<dim3(2, 32, 96), 256>>>(
        qkv + 1536, 2304, 64, TQ,
        vt, 1024, 64LL * 1024LL, 12LL * 64LL * 1024LL,
        1024, 64, 12);

    // 6) O = P @ V   (96 heads, M=1024, N=64, K=1024)
    tgemm<0><<<dim3(1, 8, 96), 256>>>(
        sc, 1024, 1024LL * 1024LL, 12LL * 1024LL * 1024LL,
        vt, 1024, 64LL * 1024LL, 12LL * 64LL * 1024LL,
        attn, 768, 64, 1024LL * 768LL,
        1024, 64, 1024, 12, nullptr, nullptr, 0, 1.0f, nullptr);

    // 7) x = x_in + O @ attn_out_w^T + b   (writes residual stream to out)
    tgemm<2><<<dim3(6, 64, 1), 256>>>(
        attn, 768, 0, 0, aow, 768, 0, 0, out, 768, 0, 0,
        8192, 768, 768, 1, aob, x, 768, 1.0f, nullptr);

    // 8) LN2
    ln_kernel<<<8192, 256>>>(out, n2g, n2b, ln);

    // 9) H = gelu(LN2 @ W1 + b1)   (N=3072)
    tgemm<3><<<dim3(24, 64, 1), 256>>>(
        ln, 768, 0, 0, wt + WT_W1, 768, 0, 0, hb, 3072, 0, 0,
        8192, 3072, 768, 1, b1, nullptr, 0, 1.0f, nullptr);

    // 10) x += H @ W2 + b2
    tgemm<2><<<dim3(6, 64, 1), 256>>>(
        hb, 3072, 0, 0, wt + WT_W2, 3072, 0, 0, out, 768, 0, 0,
        8192, 768, 3072, 1, b2, out, 768, 1.0f, nullptr);

    // 11) LN3
    ln_kernel<<<8192, 256>>>(out, n3g, n3b, ln);

    // 12) xz = LN3 @ m_in_w   (N=3072)
    tgemm<0><<<dim3(24, 64, 1), 256>>>(
        ln, 768, 0, 0, wt + WT_MIN, 768, 0, 0, hb, 3072, 0, 0,
        8192, 3072, 768, 1, nullptr, nullptr, 0, 1.0f, nullptr);

    // 13) u = silu(causal depthwise conv(xz[:, :1536]) + cb)
    conv_silu_kernel<<<49152, 256>>>(hb, cw, cb, ub);

    // 14) dbl = u @ xproj_w   (N=80, K=1536)
    tgemm<0><<<dim3(1, 64, 1), 256>>>(
        ub, 1536, 0, 0, wt + WT_XPW, 1536, 0, 0, dbl, 80, 0, 0,
        8192, 80, 1536, 1, nullptr, nullptr, 0, 1.0f, nullptr);

    // 15) dt = softplus(dbl[:, :48] @ dt_w + dt_b)   (N=1536, K=48)
    tgemm<4><<<dim3(12, 64, 1), 256>>>(
        dbl, 80, 0, 0, wt + WT_DTW, 48, 0, 0, gdt, 1536, 0, 0,
        8192, 1536, 48, 1, dtbi, nullptr, 0, 1.0f, nullptr);

    // 16) selective scan + (u*D) + *silu(res)
    scan_kernel<<<768, 256>>>(gdt, dbl, ub, hb, alog, dpar, yb);

    // 17) out = x + sigmoid(gate) * (y @ m_out_w)   (K=1536)
    tgemm<5><<<dim3(6, 64, 1), 256>>>(
        yb, 1536, 0, 0, wt + WT_MOW, 1536, 0, 0, out, 768, 0, 0,
        8192, 768, 1536, 1, nullptr, out, 768, 1.0f, gate);
}

// round 5
// speedup vs baseline: 2.8869x; 2.4288x over previous
#include <cuda_runtime.h>
#include <cuda_fp16.h>
#include <mma.h>
#include <cstdint>
#include <math.h>

using namespace nvcuda;

// ---------------------------------------------------------------------------
// MambaViTBlock: B=8, N=1024 (TOK=8192), D=768, NH=12 (dh=64), MLPH=3072,
//                DI=1536, DS=16, DTR=48, K=4
// Round 5: R4 (WMMA fp16 m16n16k16 + cp.async BK=32) with the V-transpose
// batching bug fixed (two-level zh/zb decomposition restored).
// ---------------------------------------------------------------------------

// Scratch (allocation-free static __device__ arrays)
__device__ __half g_lnh  [8192u * 768u];        // LN output (half, GEMM input)
__device__ __half g_qkvh [8192u * 2304u];       // fused QKV (half)
__device__ __half g_sch  [96u * 1024u * 1024u]; // attention scores (half)
__device__ __half g_attnh[8192u * 768u];        // attention out pre-proj
__device__ __half g_hh   [8192u * 3072u];       // MLP hidden (half)
__device__ float  g_xz   [8192u * 3072u];       // mamba xz (float: conv+res)
__device__ float  g_u    [8192u * 1536u];       // conv+silu output (float)
__device__ __half g_uh   [8192u * 1536u];       // conv+silu output (half)
__device__ float  g_dbl  [8192u * 80u];         // xproj out (dt_raw | B | C)
__device__ __half g_dblh [8192u * 64u];         // dbl[:, :48] padded to 64
__device__ float  g_dt   [8192u * 1536u];       // softplus dt
__device__ __half g_yh   [8192u * 1536u];       // scan output (half)
__device__ __half g_wth  [10838016u];           // half weights
__device__ __half g_vth  [96u * 64u * 1024u];   // transposed V per head

// offsets into g_wth (halves)
#define WH_AIW  0u
#define WH_AOW  1769472u
#define WH_W1   2359296u
#define WH_W2   4718592u
#define WH_MIN  7077888u
#define WH_MOW  9437184u
#define WH_XPW  10616832u
#define WH_DTW  10739712u

__device__ __forceinline__ float gelu_exact(float v) {
    return 0.5f * v * (1.0f + erff(v * 0.7071067811865475f));
}
__device__ __forceinline__ float softplus_f(float v) {
    return fmaxf(v, 0.0f) + log1pf(expf(-fabsf(v)));
}
__device__ __forceinline__ float silu_f(float v) {
    return v / (1.0f + expf(-v));
}

__device__ __forceinline__ uint32_t smem_u32(const void* p) {
    uint32_t a;
    asm("{ .reg .u64 t; cvta.to.shared.u64 t, %1; cvt.u32.u64 %0, t; }" : "=r"(a) : "l"(p));
    return a;
}
__device__ __forceinline__ void cp_async16(uint32_t dst, const void* src, int sz) {
    asm volatile("cp.async.ca.shared.global [%0], [%1], 16, %2;"
                 :: "r"(dst), "l"(src), "r"(sz));
}
__device__ __forceinline__ void cp_commit() { asm volatile("cp.async.commit_group;"); }
template<int N>
__device__ __forceinline__ void cp_wait() {
    asm volatile("cp.async.wait_group %0;" :: "n"(N));
}

// ---------------------------------------------------------------------------
// WMMA fp16 GEMM:  C[M,N] = epi( scale * A[M,K] @ B[N,K]^T ), fp32 accum.
//   A row-major [M,K] half; B row-major [N,K] half (K-major, NT gemm).
//   Tile 128x128, BK=32. 256 threads = 8 warps (4M x 2N), warp tile 32x64.
//   M % 128 == 0, K % 32 == 0, N % 16 == 0 (ragged by tile; zero-filled).
//   Batched via blockIdx.z -> (zh = z % ZH, zb = z / ZH).
// EPI: 0 none, 1 +bias, 2 +bias+resid, 3 gelu(+bias), 4 softplus(+bias),
//      5 resid + sigmoid(gate)*acc
// OH: output half (pure GEMM-chain buffers) vs float.
// ---------------------------------------------------------------------------
#define TLDH 40   // smem row stride in halves (80B; conflict-free LDSM)

template<int EPI, bool OH>
__global__ __launch_bounds__(256)
void tgemm(const __half* __restrict__ A, int lda, long long sAh, long long sAb,
           const __half* __restrict__ B, int ldb, long long sBh, long long sBb,
           void* __restrict__ Cv, int ldc, long long sCh, long long sCb,
           int M, int N, int K, int ZH,
           const float* __restrict__ bias,
           const float* __restrict__ resid, int ldr,
           float scale, const float* __restrict__ gatep)
{
    __shared__ __half smh[2 * 2 * 128 * TLDH];   // [stage][A|B][128][TLDH]
    const uint32_t sb = smem_u32(smh);

    const int tid = threadIdx.x;
    const int wid = tid >> 5, lid = tid & 31;
    const int warpM = wid & 3;            // 32-row slice
    const int warpN = wid >> 2;           // 64-col slice

    const int z = blockIdx.z, zh = z % ZH, zb = z / ZH;
    A += zh * sAh + (long long)zb * sAb;
    B += zh * sBh + (long long)zb * sBb;
    const long long coff = zh * sCh + (long long)zb * sCb;
    float*  Cf = (float*)Cv  + (OH ? 0 : coff);
    __half* Ch = (__half*)Cv + (OH ? coff : 0);

    const int m0 = blockIdx.y * 128, n0 = blockIdx.x * 128;
    const int NC = K / 32;

    wmma::fragment<wmma::accumulator, 16, 16, 16, float> acc[2][4];
    #pragma unroll
    for (int i = 0; i < 2; i++)
        #pragma unroll
        for (int j = 0; j < 4; j++) wmma::fill_fragment(acc[i][j], 0.0f);

    // stage: tile = 128 rows x 64B (4 chunks of 16B). 512 chunks, 2/thread.
    auto stage = [&](int c, int buf) {
        const int k0 = c * 32;
        const uint32_t offA = (uint32_t)buf * (2 * 128 * TLDH) * 2;
        const uint32_t offB = offA + (128 * TLDH) * 2;
        #pragma unroll
        for (int q = 0; q < 2; q++) {
            const int ck  = tid * 2 + q;
            const int row = ck >> 2, c16 = ck & 3;
            uint32_t da = sb + offA + (uint32_t)(row * TLDH * 2 + c16 * 16);
            cp_async16(da, A + (long long)(m0 + row) * lda + k0 + c16 * 8, 16);
            uint32_t db = sb + offB + (uint32_t)(row * TLDH * 2 + c16 * 16);
            const bool bv = (n0 + row) < N;
            const __half* bsrc = bv ? (B + (long long)(n0 + row) * ldb + k0 + c16 * 8) : B;
            cp_async16(db, bsrc, bv ? 16 : 0);
        }
    };

    auto compute = [&](int buf) {
        const __half* Asb = smh + buf * (2 * 128 * TLDH);
        const __half* Bsb = Asb + 128 * TLDH;
        #pragma unroll
        for (int kk = 0; kk < 32; kk += 16) {
            wmma::fragment<wmma::matrix_a, 16, 16, 16, __half, wmma::row_major> af[2];
            wmma::fragment<wmma::matrix_b, 16, 16, 16, __half, wmma::col_major> bf[4];
            #pragma unroll
            for (int i = 0; i < 2; i++)
                wmma::load_matrix_sync(af[i], Asb + (warpM * 32 + i * 16) * TLDH + kk, TLDH);
            #pragma unroll
            for (int j = 0; j < 4; j++)
                wmma::load_matrix_sync(bf[j], Bsb + (warpN * 64 + j * 16) * TLDH + kk, TLDH);
            #pragma unroll
            for (int i = 0; i < 2; i++)
                #pragma unroll
                for (int j = 0; j < 4; j++)
                    wmma::mma_sync(acc[i][j], af[i], bf[j], acc[i][j]);
        }
    };

    stage(0, 0);
    cp_commit();

    for (int c = 0; c < NC; c++) {
        if (c + 1 < NC) {
            stage(c + 1, (c + 1) & 1);
            cp_commit();
            cp_wait<1>();
        } else {
            cp_wait<0>();
        }
        __syncthreads();
        compute(c & 1);
        __syncthreads();
    }

    // ------- epilogue: per-warp 16x16 float patches in (reused) smem -------
    float gmul = 1.0f;
    if (EPI == 5) gmul = 1.0f / (1.0f + expf(-gatep[0]));
    float* patch = (float*)smh + wid * 256;

    #pragma unroll
    for (int i = 0; i < 2; i++) {
        #pragma unroll
        for (int j = 0; j < 4; j++) {
            const int nfrag = n0 + warpN * 64 + j * 16;
            if (nfrag >= N) continue;
            wmma::store_matrix_sync(patch, acc[i][j], 16, wmma::mem_row_major);
            __syncwarp();
            const int mbase = m0 + warpM * 32 + i * 16;
            #pragma unroll
            for (int q = 0; q < 2; q++) {
                const int idx = lid + 32 * q;       // 0..63
                const int r = idx >> 2, c4 = idx & 3;
                float4 v4 = *(const float4*)(patch + r * 16 + c4 * 4);
                const int n = nfrag + c4 * 4;
                const int m = mbase + r;
                float vv[4] = {v4.x, v4.y, v4.z, v4.w};
                #pragma unroll
                for (int qq = 0; qq < 4; qq++) {
                    float t = vv[qq] * scale;
                    if (EPI >= 1 && EPI <= 4) t += bias[n + qq];
                    if (EPI == 3) t = gelu_exact(t);
                    if (EPI == 4) t = softplus_f(t);
                    if (EPI == 2) t += resid[(long long)m * ldr + n + qq];
                    if (EPI == 5) t = resid[(long long)m * ldr + n + qq] + gmul * t;
                    vv[qq] = t;
                }
                if (OH) {
                    __half2 h0 = __floats2half2_rn(vv[0], vv[1]);
                    __half2 h1 = __floats2half2_rn(vv[2], vv[3]);
                    uint2 pk;
                    pk.x = *(uint32_t*)&h0; pk.y = *(uint32_t*)&h1;
                    *(uint2*)(Ch + (long long)m * ldc + n) = pk;
                } else {
                    *(float4*)(Cf + (long long)m * ldc + n) =
                        make_float4(vv[0], vv[1], vv[2], vv[3]);
                }
            }
            __syncwarp();
        }
    }
}

// ---------------------------------------------------------------------------
// transpose float -> half:  out[c, r] = (half) in[r, c]
// ---------------------------------------------------------------------------
__global__ __launch_bounds__(256)
void transpose_f2h(const float* __restrict__ in, int ldi,
                   __half* __restrict__ out, int ldo, int R, int C)
{
    __shared__ float t[32][33];
    const int r0 = blockIdx.y * 32, c0 = blockIdx.x * 32;
    const int tx = threadIdx.x & 31, ty = threadIdx.x >> 5;
    #pragma unroll
    for (int i = 0; i < 32; i += 8) {
        const int r = r0 + ty + i, c = c0 + tx;
        t[ty + i][tx] = (r < R && c < C) ? in[(long long)r * ldi + c] : 0.f;
    }
    __syncthreads();
    #pragma unroll
    for (int i = 0; i < 32; i += 8) {
        const int r = c0 + ty + i, c = r0 + tx;
        if (r < C && c < R) out[(long long)r * ldo + c] = __float2half_rn(t[tx][ty + i]);
    }
}

// ---------------------------------------------------------------------------
// transpose half -> half, two-level batched: z -> (zh = z%ZH, zb = z/ZH)
// ---------------------------------------------------------------------------
__global__ __launch_bounds__(256)
void transpose_h2h(const __half* __restrict__ in, int ldi, long long sIh, long long sIb,
                   __half* __restrict__ out, int ldo, long long sOh, long long sOb,
                   int R, int C, int ZH)
{
    __shared__ __half t[32][34];
    const int z = blockIdx.z, zh = z % ZH, zb = z / ZH;
    in  += zh * sIh + (long long)zb * sIb;
    out += zh * sOh + (long long)zb * sOb;
    const int r0 = blockIdx.y * 32, c0 = blockIdx.x * 32;
    const int tx = threadIdx.x & 31, ty = threadIdx.x >> 5;
    #pragma unroll
    for (int i = 0; i < 32; i += 8) {
        const int r = r0 + ty + i, c = c0 + tx;
        t[ty + i][tx] = (r < R && c < C) ? in[(long long)r * ldi + c] : __half(0.f);
    }
    __syncthreads();
    #pragma unroll
    for (int i = 0; i < 32; i += 8) {
        const int r = c0 + ty + i, c = r0 + tx;
        if (r < C && c < R) out[(long long)r * ldo + c] = t[tx][ty + i];
    }
}

// ---------------------------------------------------------------------------
// elementwise float -> half cast
// ---------------------------------------------------------------------------
__global__ __launch_bounds__(256)
void cast_f2h(const float* __restrict__ in, __half* __restrict__ out, int n)
{
    int i = blockIdx.x * 256 + threadIdx.x;
    if (i < n) out[i] = __float2half_rn(in[i]);
}

// dtw [48,1536] -> half [1536,64] transposed, K padded 48->64 with zeros
__global__ __launch_bounds__(256)
void dtw_prep(const float* __restrict__ dtw, __half* __restrict__ out)
{
    int i = blockIdx.x * 256 + threadIdx.x;   // < 1536*64
    int n = i >> 6, k = i & 63;
    out[i] = (k < 48) ? __float2half_rn(dtw[k * 1536 + n]) : __half(0.f);
}

// dbl [8192,80] -> half [8192,64], cols 48..63 zero
__global__ __launch_bounds__(256)
void dbl_prep(const float* __restrict__ dbl, __half* __restrict__ out)
{
    int i = blockIdx.x * 256 + threadIdx.x;   // < 8192*64
    int r = i >> 6, c = i & 63;
    out[i] = (c < 48) ? __float2half_rn(dbl[r * 80 + c]) : __half(0.f);
}

// ---------------------------------------------------------------------------
// LayerNorm over rows of 768, half output
// ---------------------------------------------------------------------------
__global__ __launch_bounds__(256)
void ln_kernel(const float* __restrict__ x, const float* __restrict__ g,
               const float* __restrict__ b, __half* __restrict__ y)
{
    long long row = blockIdx.x;
    const float* xr = x + row * 768;
    __half* yr = y + row * 768;
    int tid = threadIdx.x;

    float v0 = xr[tid], v1 = xr[tid + 256], v2 = xr[tid + 512];
    float s  = v0 + v1 + v2;
    float ss = v0 * v0 + v1 * v1 + v2 * v2;

    #pragma unroll
    for (int o = 16; o; o >>= 1) {
        s  += __shfl_xor_sync(0xffffffffu, s, o);
        ss += __shfl_xor_sync(0xffffffffu, ss, o);
    }
    __shared__ float sh_s[8], sh_ss[8];
    int w = tid >> 5, l = tid & 31;
    if (l == 0) { sh_s[w] = s; sh_ss[w] = ss; }
    __syncthreads();
    if (w == 0) {
        float s2  = (l < 8) ? sh_s[l]  : 0.f;
        float ss2 = (l < 8) ? sh_ss[l] : 0.f;
        #pragma unroll
        for (int o = 4; o; o >>= 1) {
            s2  += __shfl_xor_sync(0xffffffffu, s2, o);
            ss2 += __shfl_xor_sync(0xffffffffu, ss2, o);
        }
        if (l == 0) { sh_s[0] = s2; sh_ss[0] = ss2; }
    }
    __syncthreads();
    float mean = sh_s[0] * (1.0f / 768.0f);
    float var  = sh_ss[0] * (1.0f / 768.0f) - mean * mean;
    float rstd = rsqrtf(var + 1e-5f);

    yr[tid]       = __float2half_rn((v0 - mean) * rstd * g[tid]       + b[tid]);
    yr[tid + 256] = __float2half_rn((v1 - mean) * rstd * g[tid + 256] + b[tid + 256]);
    yr[tid + 512] = __float2half_rn((v2 - mean) * rstd * g[tid + 512] + b[tid + 512]);
}

// ---------------------------------------------------------------------------
// Row softmax over 1024 half columns (fp32 math)
// ---------------------------------------------------------------------------
__global__ __launch_bounds__(256)
void softmax_kernel(__half* __restrict__ S)
{
    long long row = blockIdx.x;
    __half2* p = reinterpret_cast<__half2*>(S + row * 1024);
    int tid = threadIdx.x;
    float2 a = __half22float2(p[tid]);
    float2 bq = __half22float2(p[tid + 256]);

    float mx = fmaxf(fmaxf(a.x, a.y), fmaxf(bq.x, bq.y));
    __shared__ float shm[8];
    #pragma unroll
    for (int o = 16; o; o >>= 1) mx = fmaxf(mx, __shfl_xor_sync(0xffffffffu, mx, o));
    int w = tid >> 5, l = tid & 31;
    if (l == 0) shm[w] = mx;
    __syncthreads();
    if (w == 0) {
        float m2 = (l < 8) ? shm[l] : -1e30f;
        #pragma unroll
        for (int o = 4; o; o >>= 1) m2 = fmaxf(m2, __shfl_xor_sync(0xffffffffu, m2, o));
        if (l == 0) shm[0] = m2;
    }
    __syncthreads();
    float m = shm[0];

    a.x = expf(a.x - m); a.y = expf(a.y - m);
    bq.x = expf(bq.x - m); bq.y = expf(bq.y - m);
    float s = a.x + a.y + bq.x + bq.y;
    __shared__ float shs[8];
    #pragma unroll
    for (int o = 16; o; o >>= 1) s += __shfl_xor_sync(0xffffffffu, s, o);
    if (l == 0) shs[w] = s;
    __syncthreads();
    if (w == 0) {
        float s2 = (l < 8) ? shs[l] : 0.f;
        #pragma unroll
        for (int o = 4; o; o >>= 1) s2 += __shfl_xor_sync(0xffffffffu, s2, o);
        if (l == 0) shs[0] = s2;
    }
    __syncthreads();
    float inv = 1.0f / shs[0];
    p[tid]       = __floats2half2_rn(a.x * inv, a.y * inv);
    p[tid + 256] = __floats2half2_rn(bq.x * inv, bq.y * inv);
}

// ---------------------------------------------------------------------------
// Depthwise causal conv (K=4) + bias + SiLU; float + half outputs
// ---------------------------------------------------------------------------
__global__ __launch_bounds__(256)
void conv_silu_kernel(const float* __restrict__ xz, const float* __restrict__ cw,
                      const float* __restrict__ cb, float* __restrict__ u,
                      __half* __restrict__ uh)
{
    int idx = blockIdx.x * 256 + threadIdx.x;   // < 8192*1536
    int d   = idx % 1536;
    int tok = idx / 1536;
    int t   = tok & 1023;
    float acc = cb[d];
    const float* base = xz + (long long)tok * 3072 + d;
    #pragma unroll
    for (int j = 0; j < 4; j++) {
        int tt = t - 3 + j;
        if (tt >= 0) acc = fmaf(base[(long long)(j - 3) * 3072], cw[d * 4 + j], acc);
    }
    float v = silu_f(acc);
    u [(long long)tok * 1536 + d] = v;
    uh[(long long)tok * 1536 + d] = __float2half_rn(v);
}

// ---------------------------------------------------------------------------
// Selective scan: 16 lanes per (b,d) channel; fused +u*D and *silu(res)
// ---------------------------------------------------------------------------
__global__ __launch_bounds__(256)
void scan_kernel(const float* __restrict__ dt, const float* __restrict__ dbl,
                 const float* __restrict__ u, const float* __restrict__ xz,
                 const float* __restrict__ Alog, const float* __restrict__ Dp,
                 __half* __restrict__ y)
{
    int gg = blockIdx.x * 16 + (threadIdx.x >> 4);  // (b,d) group
    int s  = threadIdx.x & 15;
    int d  = gg % 1536, b = gg / 1536;

    float A  = -expf(Alog[d * 16 + s]);
    float Dv = Dp[d];
    float h  = 0.0f;
    long long tokbase = (long long)b * 1024;

    for (int t = 0; t < 1024; t++) {
        long long tok = tokbase + t;
        float dtv = dt[tok * 1536 + d];
        float uv  = u [tok * 1536 + d];
        float Bv  = dbl[tok * 80 + 48 + s];
        float Cv  = dbl[tok * 80 + 64 + s];
        float dA  = expf(dtv * A);
        h = fmaf(dA, h, dtv * Bv * uv);
        float part = h * Cv;
        part += __shfl_xor_sync(0xffffffffu, part, 8, 16);
        part += __shfl_xor_sync(0xffffffffu, part, 4, 16);
        part += __shfl_xor_sync(0xffffffffu, part, 2, 16);
        part += __shfl_xor_sync(0xffffffffu, part, 1, 16);
        if (s == 0) {
            float rv = xz[tok * 3072 + 1536 + d];
            y[tok * 1536 + d] = __float2half_rn((part + uv * Dv) * silu_f(rv));
        }
    }
}

// ---------------------------------------------------------------------------
// Host orchestration
// ---------------------------------------------------------------------------
extern "C" void kernel_launch(void* const* d_in, const int* in_sizes, int n_in,
                              void* d_out, int out_size)
{
    const float* x    = (const float*)d_in[0];
    const float* n1g  = (const float*)d_in[1];
    const float* n1b  = (const float*)d_in[2];
    const float* aiw  = (const float*)d_in[3];
    const float* aib  = (const float*)d_in[4];
    const float* aow  = (const float*)d_in[5];
    const float* aob  = (const float*)d_in[6];
    const float* n2g  = (const float*)d_in[7];
    const float* n2b  = (const float*)d_in[8];
    const float* w1   = (const float*)d_in[9];
    const float* b1   = (const float*)d_in[10];
    const float* w2   = (const float*)d_in[11];
    const float* b2   = (const float*)d_in[12];
    const float* n3g  = (const float*)d_in[13];
    const float* n3b  = (const float*)d_in[14];
    const float* minw = (const float*)d_in[15];
    const float* cw   = (const float*)d_in[16];
    const float* cb   = (const float*)d_in[17];
    const float* xpw  = (const float*)d_in[18];
    const float* dtw  = (const float*)d_in[19];
    const float* dtbi = (const float*)d_in[20];
    const float* alog = (const float*)d_in[21];
    const float* dpar = (const float*)d_in[22];
    const float* mow  = (const float*)d_in[23];
    const float* gate = (const float*)d_in[24];
    float* out = (float*)d_out;

    __half *lnh, *qkvh, *sch, *attnh, *hh, *uh, *dblh, *yh, *wth, *vth;
    float  *xz, *ub, *dbl, *gdt;
    cudaGetSymbolAddress((void**)&lnh,   g_lnh);
    cudaGetSymbolAddress((void**)&qkvh,  g_qkvh);
    cudaGetSymbolAddress((void**)&sch,   g_sch);
    cudaGetSymbolAddress((void**)&attnh, g_attnh);
    cudaGetSymbolAddress((void**)&hh,    g_hh);
    cudaGetSymbolAddress((void**)&xz,    g_xz);
    cudaGetSymbolAddress((void**)&ub,    g_u);
    cudaGetSymbolAddress((void**)&uh,    g_uh);
    cudaGetSymbolAddress((void**)&dbl,   g_dbl);
    cudaGetSymbolAddress((void**)&dblh,  g_dblh);
    cudaGetSymbolAddress((void**)&gdt,   g_dt);
    cudaGetSymbolAddress((void**)&yh,    g_yh);
    cudaGetSymbolAddress((void**)&wth,   g_wth);
    cudaGetSymbolAddress((void**)&vth,   g_vth);

    const long long TQ = 1024LL * 2304LL;   // per-batch qkv stride (halves)

    // launches 0-4 chosen so launch index 5 (ncu -s 5) = QKV tgemm
    cast_f2h<<<(2304 * 768 + 255) / 256, 256>>>(aiw, wth + WH_AIW, 2304 * 768);   // 0
    cast_f2h<<<(768 * 768 + 255) / 256, 256>>>(aow, wth + WH_AOW, 768 * 768);     // 1
    ln_kernel<<<8192, 256>>>(x, n1g, n1b, lnh);                                   // 2
    transpose_f2h<<<dim3(96, 24, 1), 256>>>(w1, 3072, wth + WH_W1, 768, 768, 3072);  // 3
    transpose_f2h<<<dim3(24, 96, 1), 256>>>(w2, 768, wth + WH_W2, 3072, 3072, 768);  // 4

    // 5) QKV = LN1 @ attn_in_w^T + b   (M=8192, N=2304, K=768) -> half
    tgemm<1, true><<<dim3(18, 64, 1), 256>>>(
        lnh, 768, 0, 0, wth + WH_AIW, 768, 0, 0, qkvh, 2304, 0, 0,
        8192, 2304, 768, 1, aib, nullptr, 0, 1.0f, nullptr);

    // remaining weight preps
    transpose_f2h<<<dim3(96, 24, 1), 256>>>(minw, 3072, wth + WH_MIN, 768, 768, 3072);
    transpose_f2h<<<dim3(24, 48, 1), 256>>>(mow, 768, wth + WH_MOW, 1536, 1536, 768);
    transpose_f2h<<<dim3(3, 48, 1), 256>>>(xpw, 80, wth + WH_XPW, 1536, 1536, 80);
    dtw_prep<<<(1536 * 64 + 255) / 256, 256>>>(dtw, wth + WH_DTW);

    // scores = Q @ K^T / 8   (96 heads, M=N=1024, K=64) -> half
    tgemm<0, true><<<dim3(8, 8, 96), 256>>>(
        qkvh,       2304, 64, TQ,
        qkvh + 768, 2304, 64, TQ,
        sch, 1024, 1024LL * 1024LL, 12LL * 1024LL * 1024LL,
        1024, 1024, 64, 12, nullptr, nullptr, 0, 0.125f, nullptr);

    // softmax rows (half in/out)
    softmax_kernel<<<96 * 1024, 256>>>(sch);

    // V^T per head: [1024,64] -> [64,1024] half
    // in:  head offset 64 (within 2304-wide row), batch offset TQ
    // out: head offset 64*1024, batch offset 12*64*1024
    transpose_h2h<<<dim3(2, 32, 96), 256>>>(
        qkvh + 1536, 2304, 64, TQ,
        vth, 1024, 64LL * 1024LL, 12LL * 64LL * 1024LL,
        1024, 64, 12);

    // O = P @ V   (96 heads, M=1024, N=64, K=1024) -> half
    tgemm<0, true><<<dim3(1, 8, 96), 256>>>(
        sch, 1024, 1024LL * 1024LL, 12LL * 1024LL * 1024LL,
        vth, 1024, 64LL * 1024LL, 12LL * 64LL * 1024LL,
        attnh, 768, 64, 1024LL * 768LL,
        1024, 64, 1024, 12, nullptr, nullptr, 0, 1.0f, nullptr);

    // x = x_in + O @ attn_out_w^T + b   (float residual stream in out)
    tgemm<2, false><<<dim3(6, 64, 1), 256>>>(
        attnh, 768, 0, 0, wth + WH_AOW, 768, 0, 0, out, 768, 0, 0,
        8192, 768, 768, 1, aob, x, 768, 1.0f, nullptr);

    // LN2
    ln_kernel<<<8192, 256>>>(out, n2g, n2b, lnh);

    // H = gelu(LN2 @ W1 + b1)   (N=3072) -> half
    tgemm<3, true><<<dim3(24, 64, 1), 256>>>(
        lnh, 768, 0, 0, wth + WH_W1, 768, 0, 0, hh, 3072, 0, 0,
        8192, 3072, 768, 1, b1, nullptr, 0, 1.0f, nullptr);

    // x += H @ W2 + b2
    tgemm<2, false><<<dim3(6, 64, 1), 256>>>(
        hh, 3072, 0, 0, wth + WH_W2, 3072, 0, 0, out, 768, 0, 0,
        8192, 768, 3072, 1, b2, out, 768, 1.0f, nullptr);

    // LN3
    ln_kernel<<<8192, 256>>>(out, n3g, n3b, lnh);

    // xz = LN3 @ m_in_w   (N=3072) -> float (conv + res consumers)
    tgemm<0, false><<<dim3(24, 64, 1), 256>>>(
        lnh, 768, 0, 0, wth + WH_MIN, 768, 0, 0, xz, 3072, 0, 0,
        8192, 3072, 768, 1, nullptr, nullptr, 0, 1.0f, nullptr);

    // u = silu(conv(xz[:, :1536]) + cb) -> float + half
    conv_silu_kernel<<<49152, 256>>>(xz, cw, cb, ub, uh);

    // dbl = u @ xproj_w   (N=80, K=1536) -> float
    tgemm<0, false><<<dim3(1, 64, 1), 256>>>(
        uh, 1536, 0, 0, wth + WH_XPW, 1536, 0, 0, dbl, 80, 0, 0,
        8192, 80, 1536, 1, nullptr, nullptr, 0, 1.0f, nullptr);

    // dbl[:, :48] -> half padded [8192,64]
    dbl_prep<<<(8192 * 64 + 255) / 256, 256>>>(dbl, dblh);

    // dt = softplus(dbl48 @ dt_w + dt_b)   (N=1536, K=64 padded) -> float
    tgemm<4, false><<<dim3(12, 64, 1), 256>>>(
        dblh, 64, 0, 0, wth + WH_DTW, 64, 0, 0, gdt, 1536, 0, 0,
        8192, 1536, 64, 1, dtbi, nullptr, 0, 1.0f, nullptr);

    // selective scan + (u*D) + *silu(res) -> half
    scan_kernel<<<768, 256>>>(gdt, dbl, ub, xz, alog, dpar, yh);

    // out = x + sigmoid(gate) * (y @ m_out_w)   (K=1536)
    tgemm<5, false><<<dim3(6, 64, 1), 256>>>(
        yh, 1536, 0, 0, wth + WH_MOW, 1536, 0, 0, out, 768, 0, 0,
        8192, 768, 1536, 1, nullptr, out, 768, 1.0f, gate);
}

// round 6
// speedup vs baseline: 3.1895x; 1.1048x over previous
#include <cuda_runtime.h>
#include <cuda_fp16.h>
#include <mma.h>
#include <cstdint>
#include <math.h>

using namespace nvcuda;

// ---------------------------------------------------------------------------
// MambaViTBlock: B=8, N=1024 (TOK=8192), D=768, NH=12 (dh=64), MLPH=3072,
//                DI=1536, DS=16, DTR=48, K=4
// Round 6: tgemm restructured for intensity — 4 warps x (64x64) warp tiles,
// BK=64, stride-72 smem (conflict-free ldmatrix), 2-stage cp.async.
// ---------------------------------------------------------------------------

// Scratch (allocation-free static __device__ arrays)
__device__ __half g_lnh  [8192u * 768u];        // LN output (half, GEMM input)
__device__ __half g_qkvh [8192u * 2304u];       // fused QKV (half)
__device__ __half g_sch  [96u * 1024u * 1024u]; // attention scores (half)
__device__ __half g_attnh[8192u * 768u];        // attention out pre-proj
__device__ __half g_hh   [8192u * 3072u];       // MLP hidden (half)
__device__ float  g_xz   [8192u * 3072u];       // mamba xz (float: conv+res)
__device__ float  g_u    [8192u * 1536u];       // conv+silu output (float)
__device__ __half g_uh   [8192u * 1536u];       // conv+silu output (half)
__device__ float  g_dbl  [8192u * 80u];         // xproj out (dt_raw | B | C)
__device__ __half g_dblh [8192u * 64u];         // dbl[:, :48] padded to 64
__device__ float  g_dt   [8192u * 1536u];       // softplus dt
__device__ __half g_yh   [8192u * 1536u];       // scan output (half)
__device__ __half g_wth  [10838016u];           // half weights
__device__ __half g_vth  [96u * 64u * 1024u];   // transposed V per head

// offsets into g_wth (halves)
#define WH_AIW  0u
#define WH_AOW  1769472u
#define WH_W1   2359296u
#define WH_W2   4718592u
#define WH_MIN  7077888u
#define WH_MOW  9437184u
#define WH_XPW  10616832u
#define WH_DTW  10739712u

__device__ __forceinline__ float gelu_exact(float v) {
    return 0.5f * v * (1.0f + erff(v * 0.7071067811865475f));
}
__device__ __forceinline__ float softplus_f(float v) {
    return fmaxf(v, 0.0f) + log1pf(expf(-fabsf(v)));
}
__device__ __forceinline__ float silu_f(float v) {
    return v / (1.0f + expf(-v));
}

__device__ __forceinline__ uint32_t smem_u32(const void* p) {
    uint32_t a;
    asm("{ .reg .u64 t; cvta.to.shared.u64 t, %1; cvt.u32.u64 %0, t; }" : "=r"(a) : "l"(p));
    return a;
}
__device__ __forceinline__ void cp_async16(uint32_t dst, const void* src, int sz) {
    asm volatile("cp.async.ca.shared.global [%0], [%1], 16, %2;"
                 :: "r"(dst), "l"(src), "r"(sz));
}
__device__ __forceinline__ void cp_commit() { asm volatile("cp.async.commit_group;"); }
template<int N>
__device__ __forceinline__ void cp_wait() {
    asm volatile("cp.async.wait_group %0;" :: "n"(N));
}

// ---------------------------------------------------------------------------
// WMMA fp16 GEMM:  C[M,N] = epi( scale * A[M,K] @ B[N,K]^T ), fp32 accum.
//   Tile 128x128, BK=64. 128 threads = 4 warps (2M x 2N), warp tile 64x64
//   = 4x4 m16n16k16 fragments (high mma:ldmatrix ratio).
//   M % 128 == 0, K % 64 == 0, N ragged (zero-filled rows).
//   Batched via blockIdx.z -> (zh = z % ZH, zb = z / ZH).
// EPI: 0 none, 1 +bias, 2 +bias+resid, 3 gelu(+bias), 4 softplus(+bias),
//      5 resid + sigmoid(gate)*acc
// OH: output half vs float.
// ---------------------------------------------------------------------------
#define TLDH 72            // smem row stride in halves (144B; conflict-free)
#define TG_SMEM (2 * 2 * 128 * TLDH * 2)   // 2 stages x (A|B) x 128 x 72 x 2B = 73728

template<int EPI, bool OH>
__global__ __launch_bounds__(128)
void tgemm(const __half* __restrict__ A, int lda, long long sAh, long long sAb,
           const __half* __restrict__ B, int ldb, long long sBh, long long sBb,
           void* __restrict__ Cv, int ldc, long long sCh, long long sCb,
           int M, int N, int K, int ZH,
           const float* __restrict__ bias,
           const float* __restrict__ resid, int ldr,
           float scale, const float* __restrict__ gatep)
{
    extern __shared__ __half smh[];
    const uint32_t sb = smem_u32(smh);

    const int tid = threadIdx.x;
    const int wid = tid >> 5, lid = tid & 31;
    const int warpM = wid & 1;            // 64-row slice
    const int warpN = wid >> 1;           // 64-col slice

    const int z = blockIdx.z, zh = z % ZH, zb = z / ZH;
    A += zh * sAh + (long long)zb * sAb;
    B += zh * sBh + (long long)zb * sBb;
    const long long coff = zh * sCh + (long long)zb * sCb;
    float*  Cf = (float*)Cv  + (OH ? 0 : coff);
    __half* Ch = (__half*)Cv + (OH ? coff : 0);

    const int m0 = blockIdx.y * 128, n0 = blockIdx.x * 128;
    const int NC = K / 64;

    wmma::fragment<wmma::accumulator, 16, 16, 16, float> acc[4][4];
    #pragma unroll
    for (int i = 0; i < 4; i++)
        #pragma unroll
        for (int j = 0; j < 4; j++) wmma::fill_fragment(acc[i][j], 0.0f);

    // stage: per op 128 rows x 128B = 1024 chunks of 16B; 8 per thread.
    auto stage = [&](int c, int buf) {
        const int k0 = c * 64;
        const uint32_t offA = (uint32_t)buf * (2 * 128 * TLDH) * 2;
        const uint32_t offB = offA + (128 * TLDH) * 2;
        #pragma unroll
        for (int q = 0; q < 8; q++) {
            const int id  = q * 128 + tid;
            const int row = id >> 3, c16 = id & 7;
            const uint32_t so = (uint32_t)(row * (TLDH * 2) + c16 * 16);
            cp_async16(sb + offA + so,
                       A + (long long)(m0 + row) * lda + k0 + c16 * 8, 16);
            const bool bv = (n0 + row) < N;
            const __half* bsrc = bv ? (B + (long long)(n0 + row) * ldb + k0 + c16 * 8) : B;
            cp_async16(sb + offB + so, bsrc, bv ? 16 : 0);
        }
    };

    auto compute = [&](int buf) {
        const __half* Asb = smh + buf * (2 * 128 * TLDH);
        const __half* Bsb = Asb + 128 * TLDH;
        #pragma unroll
        for (int kk = 0; kk < 64; kk += 16) {
            wmma::fragment<wmma::matrix_a, 16, 16, 16, __half, wmma::row_major> af[4];
            #pragma unroll
            for (int i = 0; i < 4; i++)
                wmma::load_matrix_sync(af[i], Asb + (warpM * 64 + i * 16) * TLDH + kk, TLDH);
            #pragma unroll
            for (int j = 0; j < 4; j++) {
                wmma::fragment<wmma::matrix_b, 16, 16, 16, __half, wmma::col_major> bf;
                wmma::load_matrix_sync(bf, Bsb + (warpN * 64 + j * 16) * TLDH + kk, TLDH);
                #pragma unroll
                for (int i = 0; i < 4; i++)
                    wmma::mma_sync(acc[i][j], af[i], bf, acc[i][j]);
            }
        }
    };

    stage(0, 0);
    cp_commit();

    for (int c = 0; c < NC; c++) {
        if (c + 1 < NC) {
            stage(c + 1, (c + 1) & 1);
            cp_commit();
            cp_wait<1>();
        } else {
            cp_wait<0>();
        }
        __syncthreads();
        compute(c & 1);
        __syncthreads();
    }

    // ------- epilogue: per-warp 16x16 float patches in (reused) smem -------
    float gmul = 1.0f;
    if (EPI == 5) gmul = 1.0f / (1.0f + expf(-gatep[0]));
    float* patch = (float*)smh + wid * 256;

    #pragma unroll
    for (int i = 0; i < 4; i++) {
        #pragma unroll
        for (int j = 0; j < 4; j++) {
            const int nfrag = n0 + warpN * 64 + j * 16;
            if (nfrag >= N) continue;
            wmma::store_matrix_sync(patch, acc[i][j], 16, wmma::mem_row_major);
            __syncwarp();
            const int mbase = m0 + warpM * 64 + i * 16;
            #pragma unroll
            for (int q = 0; q < 2; q++) {
                const int idx = lid + 32 * q;       // 0..63
                const int r = idx >> 2, c4 = idx & 3;
                float4 v4 = *(const float4*)(patch + r * 16 + c4 * 4);
                const int n = nfrag + c4 * 4;
                const int m = mbase + r;
                float vv[4] = {v4.x, v4.y, v4.z, v4.w};
                #pragma unroll
                for (int qq = 0; qq < 4; qq++) {
                    float t = vv[qq] * scale;
                    if (EPI >= 1 && EPI <= 4) t += bias[n + qq];
                    if (EPI == 3) t = gelu_exact(t);
                    if (EPI == 4) t = softplus_f(t);
                    if (EPI == 2) t += resid[(long long)m * ldr + n + qq];
                    if (EPI == 5) t = resid[(long long)m * ldr + n + qq] + gmul * t;
                    vv[qq] = t;
                }
                if (OH) {
                    __half2 h0 = __floats2half2_rn(vv[0], vv[1]);
                    __half2 h1 = __floats2half2_rn(vv[2], vv[3]);
                    uint2 pk;
                    pk.x = *(uint32_t*)&h0; pk.y = *(uint32_t*)&h1;
                    *(uint2*)(Ch + (long long)m * ldc + n) = pk;
                } else {
                    *(float4*)(Cf + (long long)m * ldc + n) =
                        make_float4(vv[0], vv[1], vv[2], vv[3]);
                }
            }
            __syncwarp();
        }
    }
}

// ---------------------------------------------------------------------------
// transpose float -> half:  out[c, r] = (half) in[r, c]
// ---------------------------------------------------------------------------
__global__ __launch_bounds__(256)
void transpose_f2h(const float* __restrict__ in, int ldi,
                   __half* __restrict__ out, int ldo, int R, int C)
{
    __shared__ float t[32][33];
    const int r0 = blockIdx.y * 32, c0 = blockIdx.x * 32;
    const int tx = threadIdx.x & 31, ty = threadIdx.x >> 5;
    #pragma unroll
    for (int i = 0; i < 32; i += 8) {
        const int r = r0 + ty + i, c = c0 + tx;
        t[ty + i][tx] = (r < R && c < C) ? in[(long long)r * ldi + c] : 0.f;
    }
    __syncthreads();
    #pragma unroll
    for (int i = 0; i < 32; i += 8) {
        const int r = c0 + ty + i, c = r0 + tx;
        if (r < C && c < R) out[(long long)r * ldo + c] = __float2half_rn(t[tx][ty + i]);
    }
}

// ---------------------------------------------------------------------------
// transpose half -> half, two-level batched: z -> (zh = z%ZH, zb = z/ZH)
// ---------------------------------------------------------------------------
__global__ __launch_bounds__(256)
void transpose_h2h(const __half* __restrict__ in, int ldi, long long sIh, long long sIb,
                   __half* __restrict__ out, int ldo, long long sOh, long long sOb,
                   int R, int C, int ZH)
{
    __shared__ __half t[32][34];
    const int z = blockIdx.z, zh = z % ZH, zb = z / ZH;
    in  += zh * sIh + (long long)zb * sIb;
    out += zh * sOh + (long long)zb * sOb;
    const int r0 = blockIdx.y * 32, c0 = blockIdx.x * 32;
    const int tx = threadIdx.x & 31, ty = threadIdx.x >> 5;
    #pragma unroll
    for (int i = 0; i < 32; i += 8) {
        const int r = r0 + ty + i, c = c0 + tx;
        t[ty + i][tx] = (r < R && c < C) ? in[(long long)r * ldi + c] : __half(0.f);
    }
    __syncthreads();
    #pragma unroll
    for (int i = 0; i < 32; i += 8) {
        const int r = c0 + ty + i, c = r0 + tx;
        if (r < C && c < R) out[(long long)r * ldo + c] = t[tx][ty + i];
    }
}

// ---------------------------------------------------------------------------
// elementwise float -> half cast
// ---------------------------------------------------------------------------
__global__ __launch_bounds__(256)
void cast_f2h(const float* __restrict__ in, __half* __restrict__ out, int n)
{
    int i = blockIdx.x * 256 + threadIdx.x;
    if (i < n) out[i] = __float2half_rn(in[i]);
}

// dtw [48,1536] -> half [1536,64] transposed, K padded 48->64 with zeros
__global__ __launch_bounds__(256)
void dtw_prep(const float* __restrict__ dtw, __half* __restrict__ out)
{
    int i = blockIdx.x * 256 + threadIdx.x;   // < 1536*64
    int n = i >> 6, k = i & 63;
    out[i] = (k < 48) ? __float2half_rn(dtw[k * 1536 + n]) : __half(0.f);
}

// dbl [8192,80] -> half [8192,64], cols 48..63 zero
__global__ __launch_bounds__(256)
void dbl_prep(const float* __restrict__ dbl, __half* __restrict__ out)
{
    int i = blockIdx.x * 256 + threadIdx.x;   // < 8192*64
    int r = i >> 6, c = i & 63;
    out[i] = (c < 48) ? __float2half_rn(dbl[r * 80 + c]) : __half(0.f);
}

// ---------------------------------------------------------------------------
// LayerNorm over rows of 768, half output
// ---------------------------------------------------------------------------
__global__ __launch_bounds__(256)
void ln_kernel(const float* __restrict__ x, const float* __restrict__ g,
               const float* __restrict__ b, __half* __restrict__ y)
{
    long long row = blockIdx.x;
    const float* xr = x + row * 768;
    __half* yr = y + row * 768;
    int tid = threadIdx.x;

    float v0 = xr[tid], v1 = xr[tid + 256], v2 = xr[tid + 512];
    float s  = v0 + v1 + v2;
    float ss = v0 * v0 + v1 * v1 + v2 * v2;

    #pragma unroll
    for (int o = 16; o; o >>= 1) {
        s  += __shfl_xor_sync(0xffffffffu, s, o);
        ss += __shfl_xor_sync(0xffffffffu, ss, o);
    }
    __shared__ float sh_s[8], sh_ss[8];
    int w = tid >> 5, l = tid & 31;
    if (l == 0) { sh_s[w] = s; sh_ss[w] = ss; }
    __syncthreads();
    if (w == 0) {
        float s2  = (l < 8) ? sh_s[l]  : 0.f;
        float ss2 = (l < 8) ? sh_ss[l] : 0.f;
        #pragma unroll
        for (int o = 4; o; o >>= 1) {
            s2  += __shfl_xor_sync(0xffffffffu, s2, o);
            ss2 += __shfl_xor_sync(0xffffffffu, ss2, o);
        }
        if (l == 0) { sh_s[0] = s2; sh_ss[0] = ss2; }
    }
    __syncthreads();
    float mean = sh_s[0] * (1.0f / 768.0f);
    float var  = sh_ss[0] * (1.0f / 768.0f) - mean * mean;
    float rstd = rsqrtf(var + 1e-5f);

    yr[tid]       = __float2half_rn((v0 - mean) * rstd * g[tid]       + b[tid]);
    yr[tid + 256] = __float2half_rn((v1 - mean) * rstd * g[tid + 256] + b[tid + 256]);
    yr[tid + 512] = __float2half_rn((v2 - mean) * rstd * g[tid + 512] + b[tid + 512]);
}

// ---------------------------------------------------------------------------
// Row softmax over 1024 half columns (fp32 math)
// ---------------------------------------------------------------------------
__global__ __launch_bounds__(256)
void softmax_kernel(__half* __restrict__ S)
{
    long long row = blockIdx.x;
    __half2* p = reinterpret_cast<__half2*>(S + row * 1024);
    int tid = threadIdx.x;
    float2 a = __half22float2(p[tid]);
    float2 bq = __half22float2(p[tid + 256]);

    float mx = fmaxf(fmaxf(a.x, a.y), fmaxf(bq.x, bq.y));
    __shared__ float shm[8];
    #pragma unroll
    for (int o = 16; o; o >>= 1) mx = fmaxf(mx, __shfl_xor_sync(0xffffffffu, mx, o));
    int w = tid >> 5, l = tid & 31;
    if (l == 0) shm[w] = mx;
    __syncthreads();
    if (w == 0) {
        float m2 = (l < 8) ? shm[l] : -1e30f;
        #pragma unroll
        for (int o = 4; o; o >>= 1) m2 = fmaxf(m2, __shfl_xor_sync(0xffffffffu, m2, o));
        if (l == 0) shm[0] = m2;
    }
    __syncthreads();
    float m = shm[0];

    a.x = expf(a.x - m); a.y = expf(a.y - m);
    bq.x = expf(bq.x - m); bq.y = expf(bq.y - m);
    float s = a.x + a.y + bq.x + bq.y;
    __shared__ float shs[8];
    #pragma unroll
    for (int o = 16; o; o >>= 1) s += __shfl_xor_sync(0xffffffffu, s, o);
    if (l == 0) shs[w] = s;
    __syncthreads();
    if (w == 0) {
        float s2 = (l < 8) ? shs[l] : 0.f;
        #pragma unroll
        for (int o = 4; o; o >>= 1) s2 += __shfl_xor_sync(0xffffffffu, s2, o);
        if (l == 0) shs[0] = s2;
    }
    __syncthreads();
    float inv = 1.0f / shs[0];
    p[tid]       = __floats2half2_rn(a.x * inv, a.y * inv);
    p[tid + 256] = __floats2half2_rn(bq.x * inv, bq.y * inv);
}

// ---------------------------------------------------------------------------
// Depthwise causal conv (K=4) + bias + SiLU; float + half outputs
// ---------------------------------------------------------------------------
__global__ __launch_bounds__(256)
void conv_silu_kernel(const float* __restrict__ xz, const float* __restrict__ cw,
                      const float* __restrict__ cb, float* __restrict__ u,
                      __half* __restrict__ uh)
{
    int idx = blockIdx.x * 256 + threadIdx.x;   // < 8192*1536
    int d   = idx % 1536;
    int tok = idx / 1536;
    int t   = tok & 1023;
    float acc = cb[d];
    const float* base = xz + (long long)tok * 3072 + d;
    #pragma unroll
    for (int j = 0; j < 4; j++) {
        int tt = t - 3 + j;
        if (tt >= 0) acc = fmaf(base[(long long)(j - 3) * 3072], cw[d * 4 + j], acc);
    }
    float v = silu_f(acc);
    u [(long long)tok * 1536 + d] = v;
    uh[(long long)tok * 1536 + d] = __float2half_rn(v);
}

// ---------------------------------------------------------------------------
// Selective scan: 16 lanes per (b,d) channel; fused +u*D and *silu(res)
// ---------------------------------------------------------------------------
__global__ __launch_bounds__(256)
void scan_kernel(const float* __restrict__ dt, const float* __restrict__ dbl,
                 const float* __restrict__ u, const float* __restrict__ xz,
                 const float* __restrict__ Alog, const float* __restrict__ Dp,
                 __half* __restrict__ y)
{
    int gg = blockIdx.x * 16 + (threadIdx.x >> 4);  // (b,d) group
    int s  = threadIdx.x & 15;
    int d  = gg % 1536, b = gg / 1536;

    float A  = -expf(Alog[d * 16 + s]);
    float Dv = Dp[d];
    float h  = 0.0f;
    long long tokbase = (long long)b * 1024;

    for (int t = 0; t < 1024; t++) {
        long long tok = tokbase + t;
        float dtv = dt[tok * 1536 + d];
        float uv  = u [tok * 1536 + d];
        float Bv  = dbl[tok * 80 + 48 + s];
        float Cv  = dbl[tok * 80 + 64 + s];
        float dA  = expf(dtv * A);
        h = fmaf(dA, h, dtv * Bv * uv);
        float part = h * Cv;
        part += __shfl_xor_sync(0xffffffffu, part, 8, 16);
        part += __shfl_xor_sync(0xffffffffu, part, 4, 16);
        part += __shfl_xor_sync(0xffffffffu, part, 2, 16);
        part += __shfl_xor_sync(0xffffffffu, part, 1, 16);
        if (s == 0) {
            float rv = xz[tok * 3072 + 1536 + d];
            y[tok * 1536 + d] = __float2half_rn((part + uv * Dv) * silu_f(rv));
        }
    }
}

// ---------------------------------------------------------------------------
// Host orchestration
// ---------------------------------------------------------------------------
extern "C" void kernel_launch(void* const* d_in, const int* in_sizes, int n_in,
                              void* d_out, int out_size)
{
    const float* x    = (const float*)d_in[0];
    const float* n1g  = (const float*)d_in[1];
    const float* n1b  = (const float*)d_in[2];
    const float* aiw  = (const float*)d_in[3];
    const float* aib  = (const float*)d_in[4];
    const float* aow  = (const float*)d_in[5];
    const float* aob  = (const float*)d_in[6];
    const float* n2g  = (const float*)d_in[7];
    const float* n2b  = (const float*)d_in[8];
    const float* w1   = (const float*)d_in[9];
    const float* b1   = (const float*)d_in[10];
    const float* w2   = (const float*)d_in[11];
    const float* b2   = (const float*)d_in[12];
    const float* n3g  = (const float*)d_in[13];
    const float* n3b  = (const float*)d_in[14];
    const float* minw = (const float*)d_in[15];
    const float* cw   = (const float*)d_in[16];
    const float* cb   = (const float*)d_in[17];
    const float* xpw  = (const float*)d_in[18];
    const float* dtw  = (const float*)d_in[19];
    const float* dtbi = (const float*)d_in[20];
    const float* alog = (const float*)d_in[21];
    const float* dpar = (const float*)d_in[22];
    const float* mow  = (const float*)d_in[23];
    const float* gate = (const float*)d_in[24];
    float* out = (float*)d_out;

    __half *lnh, *qkvh, *sch, *attnh, *hh, *uh, *dblh, *yh, *wth, *vth;
    float  *xz, *ub, *dbl, *gdt;
    cudaGetSymbolAddress((void**)&lnh,   g_lnh);
    cudaGetSymbolAddress((void**)&qkvh,  g_qkvh);
    cudaGetSymbolAddress((void**)&sch,   g_sch);
    cudaGetSymbolAddress((void**)&attnh, g_attnh);
    cudaGetSymbolAddress((void**)&hh,    g_hh);
    cudaGetSymbolAddress((void**)&xz,    g_xz);
    cudaGetSymbolAddress((void**)&ub,    g_u);
    cudaGetSymbolAddress((void**)&uh,    g_uh);
    cudaGetSymbolAddress((void**)&dbl,   g_dbl);
    cudaGetSymbolAddress((void**)&dblh,  g_dblh);
    cudaGetSymbolAddress((void**)&gdt,   g_dt);
    cudaGetSymbolAddress((void**)&yh,    g_yh);
    cudaGetSymbolAddress((void**)&wth,   g_wth);
    cudaGetSymbolAddress((void**)&vth,   g_vth);

    // raise dynamic smem limit for all tgemm instantiations used (idempotent)
    cudaFuncSetAttribute(tgemm<0, true>,  cudaFuncAttributeMaxDynamicSharedMemorySize, TG_SMEM);
    cudaFuncSetAttribute(tgemm<1, true>,  cudaFuncAttributeMaxDynamicSharedMemorySize, TG_SMEM);
    cudaFuncSetAttribute(tgemm<3, true>,  cudaFuncAttributeMaxDynamicSharedMemorySize, TG_SMEM);
    cudaFuncSetAttribute(tgemm<0, false>, cudaFuncAttributeMaxDynamicSharedMemorySize, TG_SMEM);
    cudaFuncSetAttribute(tgemm<2, false>, cudaFuncAttributeMaxDynamicSharedMemorySize, TG_SMEM);
    cudaFuncSetAttribute(tgemm<4, false>, cudaFuncAttributeMaxDynamicSharedMemorySize, TG_SMEM);
    cudaFuncSetAttribute(tgemm<5, false>, cudaFuncAttributeMaxDynamicSharedMemorySize, TG_SMEM);

    const long long TQ = 1024LL * 2304LL;   // per-batch qkv stride (halves)

    // weight preps
    cast_f2h<<<(2304 * 768 + 255) / 256, 256>>>(aiw, wth + WH_AIW, 2304 * 768);
    cast_f2h<<<(768 * 768 + 255) / 256, 256>>>(aow, wth + WH_AOW, 768 * 768);
    ln_kernel<<<8192, 256>>>(x, n1g, n1b, lnh);
    transpose_f2h<<<dim3(96, 24, 1), 256>>>(w1, 3072, wth + WH_W1, 768, 768, 3072);
    transpose_f2h<<<dim3(24, 96, 1), 256>>>(w2, 768, wth + WH_W2, 3072, 3072, 768);

    // QKV = LN1 @ attn_in_w^T + b   (M=8192, N=2304, K=768) -> half
    tgemm<1, true><<<dim3(18, 64, 1), 128, TG_SMEM>>>(
        lnh, 768, 0, 0, wth + WH_AIW, 768, 0, 0, qkvh, 2304, 0, 0,
        8192, 2304, 768, 1, aib, nullptr, 0, 1.0f, nullptr);

    transpose_f2h<<<dim3(96, 24, 1), 256>>>(minw, 3072, wth + WH_MIN, 768, 768, 3072);
    transpose_f2h<<<dim3(24, 48, 1), 256>>>(mow, 768, wth + WH_MOW, 1536, 1536, 768);
    transpose_f2h<<<dim3(3, 48, 1), 256>>>(xpw, 80, wth + WH_XPW, 1536, 1536, 80);
    dtw_prep<<<(1536 * 64 + 255) / 256, 256>>>(dtw, wth + WH_DTW);

    // scores = Q @ K^T / 8   (96 heads, M=N=1024, K=64) -> half
    tgemm<0, true><<<dim3(8, 8, 96), 128, TG_SMEM>>>(
        qkvh,       2304, 64, TQ,
        qkvh + 768, 2304, 64, TQ,
        sch, 1024, 1024LL * 1024LL, 12LL * 1024LL * 1024LL,
        1024, 1024, 64, 12, nullptr, nullptr, 0, 0.125f, nullptr);

    // softmax rows (half in/out)
    softmax_kernel<<<96 * 1024, 256>>>(sch);

    // V^T per head: [1024,64] -> [64,1024] half (zh stride 64, zb stride TQ)
    transpose_h2h<<<dim3(2, 32, 96), 256>>>(
        qkvh + 1536, 2304, 64, TQ,
        vth, 1024, 64LL * 1024LL, 12LL * 64LL * 1024LL,
        1024, 64, 12);

    // O = P @ V   (96 heads, M=1024, N=64, K=1024) -> half
    tgemm<0, true><<<dim3(1, 8, 96), 128, TG_SMEM>>>(
        sch, 1024, 1024LL * 1024LL, 12LL * 1024LL * 1024LL,
        vth, 1024, 64LL * 1024LL, 12LL * 64LL * 1024LL,
        attnh, 768, 64, 1024LL * 768LL,
        1024, 64, 1024, 12, nullptr, nullptr, 0, 1.0f, nullptr);

    // x = x_in + O @ attn_out_w^T + b   (float residual stream in out)
    tgemm<2, false><<<dim3(6, 64, 1), 128, TG_SMEM>>>(
        attnh, 768, 0, 0, wth + WH_AOW, 768, 0, 0, out, 768, 0, 0,
        8192, 768, 768, 1, aob, x, 768, 1.0f, nullptr);

    // LN2
    ln_kernel<<<8192, 256>>>(out, n2g, n2b, lnh);

    // H = gelu(LN2 @ W1 + b1)   (N=3072) -> half
    tgemm<3, true><<<dim3(24, 64, 1), 128, TG_SMEM>>>(
        lnh, 768, 0, 0, wth + WH_W1, 768, 0, 0, hh, 3072, 0, 0,
        8192, 3072, 768, 1, b1, nullptr, 0, 1.0f, nullptr);

    // x += H @ W2 + b2
    tgemm<2, false><<<dim3(6, 64, 1), 128, TG_SMEM>>>(
        hh, 3072, 0, 0, wth + WH_W2, 3072, 0, 0, out, 768, 0, 0,
        8192, 768, 3072, 1, b2, out, 768, 1.0f, nullptr);

    // LN3
    ln_kernel<<<8192, 256>>>(out, n3g, n3b, lnh);

    // xz = LN3 @ m_in_w   (N=3072) -> float (conv + res consumers)
    tgemm<0, false><<<dim3(24, 64, 1), 128, TG_SMEM>>>(
        lnh, 768, 0, 0, wth + WH_MIN, 768, 0, 0, xz, 3072, 0, 0,
        8192, 3072, 768, 1, nullptr, nullptr, 0, 1.0f, nullptr);

    // u = silu(conv(xz[:, :1536]) + cb) -> float + half
    conv_silu_kernel<<<49152, 256>>>(xz, cw, cb, ub, uh);

    // dbl = u @ xproj_w   (N=80, K=1536) -> float
    tgemm<0, false><<<dim3(1, 64, 1), 128, TG_SMEM>>>(
        uh, 1536, 0, 0, wth + WH_XPW, 1536, 0, 0, dbl, 80, 0, 0,
        8192, 80, 1536, 1, nullptr, nullptr, 0, 1.0f, nullptr);

    // dbl[:, :48] -> half padded [8192,64]
    dbl_prep<<<(8192 * 64 + 255) / 256, 256>>>(dbl, dblh);

    // dt = softplus(dbl48 @ dt_w + dt_b)   (N=1536, K=64 padded) -> float
    tgemm<4, false><<<dim3(12, 64, 1), 128, TG_SMEM>>>(
        dblh, 64, 0, 0, wth + WH_DTW, 64, 0, 0, gdt, 1536, 0, 0,
        8192, 1536, 64, 1, dtbi, nullptr, 0, 1.0f, nullptr);

    // selective scan + (u*D) + *silu(res) -> half
    scan_kernel<<<768, 256>>>(gdt, dbl, ub, xz, alog, dpar, yh);

    // out = x + sigmoid(gate) * (y @ m_out_w)   (K=1536)
    tgemm<5, false><<<dim3(6, 64, 1), 128, TG_SMEM>>>(
        yh, 1536, 0, 0, wth + WH_MOW, 1536, 0, 0, out, 768, 0, 0,
        8192, 768, 1536, 1, nullptr, out, 768, 1.0f, gate);
}

// round 7
// speedup vs baseline: 3.3557x; 1.0521x over previous
#include <cuda_runtime.h>
#include <cuda_fp16.h>
#include <mma.h>
#include <cstdint>
#include <math.h>

using namespace nvcuda;

// ---------------------------------------------------------------------------
// MambaViTBlock: B=8, N=1024 (TOK=8192), D=768, NH=12 (dh=64), MLPH=3072,
//                DI=1536, DS=16, DTR=48, K=4
// Round 7: fused flash attention (QK^T -> exp -> PV, streaming, unnormalized
// accumulate + final divide) replaces scores GEMM + softmax + V transpose +
// PV GEMM. GEMM core unchanged from R6 (WMMA fp16, 64x64 warp tiles, BK=64).
// ---------------------------------------------------------------------------

// Scratch (allocation-free static __device__ arrays)
__device__ __half g_lnh  [8192u * 768u];        // LN output (half, GEMM input)
__device__ __half g_qkvh [8192u * 2304u];       // fused QKV (half)
__device__ __half g_attnh[8192u * 768u];        // attention out pre-proj
__device__ __half g_hh   [8192u * 3072u];       // MLP hidden (half)
__device__ float  g_xz   [8192u * 3072u];       // mamba xz (float: conv+res)
__device__ float  g_u    [8192u * 1536u];       // conv+silu output (float)
__device__ __half g_uh   [8192u * 1536u];       // conv+silu output (half)
__device__ float  g_dbl  [8192u * 80u];         // xproj out (dt_raw | B | C)
__device__ __half g_dblh [8192u * 64u];         // dbl[:, :48] padded to 64
__device__ float  g_dt   [8192u * 1536u];       // softplus dt
__device__ __half g_yh   [8192u * 1536u];       // scan output (half)
__device__ __half g_wth  [10838016u];           // half weights

// offsets into g_wth (halves)
#define WH_AIW  0u
#define WH_AOW  1769472u
#define WH_W1   2359296u
#define WH_W2   4718592u
#define WH_MIN  7077888u
#define WH_MOW  9437184u
#define WH_XPW  10616832u
#define WH_DTW  10739712u

__device__ __forceinline__ float gelu_exact(float v) {
    return 0.5f * v * (1.0f + erff(v * 0.7071067811865475f));
}
__device__ __forceinline__ float softplus_f(float v) {
    return fmaxf(v, 0.0f) + log1pf(expf(-fabsf(v)));
}
__device__ __forceinline__ float silu_f(float v) {
    return v / (1.0f + expf(-v));
}

__device__ __forceinline__ uint32_t smem_u32(const void* p) {
    uint32_t a;
    asm("{ .reg .u64 t; cvta.to.shared.u64 t, %1; cvt.u32.u64 %0, t; }" : "=r"(a) : "l"(p));
    return a;
}
__device__ __forceinline__ void cp_async16(uint32_t dst, const void* src, int sz) {
    asm volatile("cp.async.ca.shared.global [%0], [%1], 16, %2;"
                 :: "r"(dst), "l"(src), "r"(sz));
}
__device__ __forceinline__ void cp_commit() { asm volatile("cp.async.commit_group;"); }
template<int N>
__device__ __forceinline__ void cp_wait() {
    asm volatile("cp.async.wait_group %0;" :: "n"(N));
}

// ---------------------------------------------------------------------------
// WMMA fp16 GEMM (unchanged from R6): C[M,N] = epi( scale * A @ B^T )
// ---------------------------------------------------------------------------
#define TLDH 72            // smem row stride in halves (144B)
#define TG_SMEM (2 * 2 * 128 * TLDH * 2)   // 73728 B

template<int EPI, bool OH>
__global__ __launch_bounds__(128)
void tgemm(const __half* __restrict__ A, int lda, long long sAh, long long sAb,
           const __half* __restrict__ B, int ldb, long long sBh, long long sBb,
           void* __restrict__ Cv, int ldc, long long sCh, long long sCb,
           int M, int N, int K, int ZH,
           const float* __restrict__ bias,
           const float* __restrict__ resid, int ldr,
           float scale, const float* __restrict__ gatep)
{
    extern __shared__ __half smh[];
    const uint32_t sb = smem_u32(smh);

    const int tid = threadIdx.x;
    const int wid = tid >> 5, lid = tid & 31;
    const int warpM = wid & 1;
    const int warpN = wid >> 1;

    const int z = blockIdx.z, zh = z % ZH, zb = z / ZH;
    A += zh * sAh + (long long)zb * sAb;
    B += zh * sBh + (long long)zb * sBb;
    const long long coff = zh * sCh + (long long)zb * sCb;
    float*  Cf = (float*)Cv  + (OH ? 0 : coff);
    __half* Ch = (__half*)Cv + (OH ? coff : 0);

    const int m0 = blockIdx.y * 128, n0 = blockIdx.x * 128;
    const int NC = K / 64;

    wmma::fragment<wmma::accumulator, 16, 16, 16, float> acc[4][4];
    #pragma unroll
    for (int i = 0; i < 4; i++)
        #pragma unroll
        for (int j = 0; j < 4; j++) wmma::fill_fragment(acc[i][j], 0.0f);

    auto stage = [&](int c, int buf) {
        const int k0 = c * 64;
        const uint32_t offA = (uint32_t)buf * (2 * 128 * TLDH) * 2;
        const uint32_t offB = offA + (128 * TLDH) * 2;
        #pragma unroll
        for (int q = 0; q < 8; q++) {
            const int id  = q * 128 + tid;
            const int row = id >> 3, c16 = id & 7;
            const uint32_t so = (uint32_t)(row * (TLDH * 2) + c16 * 16);
            cp_async16(sb + offA + so,
                       A + (long long)(m0 + row) * lda + k0 + c16 * 8, 16);
            const bool bv = (n0 + row) < N;
            const __half* bsrc = bv ? (B + (long long)(n0 + row) * ldb + k0 + c16 * 8) : B;
            cp_async16(sb + offB + so, bsrc, bv ? 16 : 0);
        }
    };

    auto compute = [&](int buf) {
        const __half* Asb = smh + buf * (2 * 128 * TLDH);
        const __half* Bsb = Asb + 128 * TLDH;
        #pragma unroll
        for (int kk = 0; kk < 64; kk += 16) {
            wmma::fragment<wmma::matrix_a, 16, 16, 16, __half, wmma::row_major> af[4];
            #pragma unroll
            for (int i = 0; i < 4; i++)
                wmma::load_matrix_sync(af[i], Asb + (warpM * 64 + i * 16) * TLDH + kk, TLDH);
            #pragma unroll
            for (int j = 0; j < 4; j++) {
                wmma::fragment<wmma::matrix_b, 16, 16, 16, __half, wmma::col_major> bf;
                wmma::load_matrix_sync(bf, Bsb + (warpN * 64 + j * 16) * TLDH + kk, TLDH);
                #pragma unroll
                for (int i = 0; i < 4; i++)
                    wmma::mma_sync(acc[i][j], af[i], bf, acc[i][j]);
            }
        }
    };

    stage(0, 0);
    cp_commit();

    for (int c = 0; c < NC; c++) {
        if (c + 1 < NC) {
            stage(c + 1, (c + 1) & 1);
            cp_commit();
            cp_wait<1>();
        } else {
            cp_wait<0>();
        }
        __syncthreads();
        compute(c & 1);
        __syncthreads();
    }

    float gmul = 1.0f;
    if (EPI == 5) gmul = 1.0f / (1.0f + expf(-gatep[0]));
    float* patch = (float*)smh + wid * 256;

    #pragma unroll
    for (int i = 0; i < 4; i++) {
        #pragma unroll
        for (int j = 0; j < 4; j++) {
            const int nfrag = n0 + warpN * 64 + j * 16;
            if (nfrag >= N) continue;
            wmma::store_matrix_sync(patch, acc[i][j], 16, wmma::mem_row_major);
            __syncwarp();
            const int mbase = m0 + warpM * 64 + i * 16;
            #pragma unroll
            for (int q = 0; q < 2; q++) {
                const int idx = lid + 32 * q;
                const int r = idx >> 2, c4 = idx & 3;
                float4 v4 = *(const float4*)(patch + r * 16 + c4 * 4);
                const int n = nfrag + c4 * 4;
                const int m = mbase + r;
                float vv[4] = {v4.x, v4.y, v4.z, v4.w};
                #pragma unroll
                for (int qq = 0; qq < 4; qq++) {
                    float t = vv[qq] * scale;
                    if (EPI >= 1 && EPI <= 4) t += bias[n + qq];
                    if (EPI == 3) t = gelu_exact(t);
                    if (EPI == 4) t = softplus_f(t);
                    if (EPI == 2) t += resid[(long long)m * ldr + n + qq];
                    if (EPI == 5) t = resid[(long long)m * ldr + n + qq] + gmul * t;
                    vv[qq] = t;
                }
                if (OH) {
                    __half2 h0 = __floats2half2_rn(vv[0], vv[1]);
                    __half2 h1 = __floats2half2_rn(vv[2], vv[3]);
                    uint2 pk;
                    pk.x = *(uint32_t*)&h0; pk.y = *(uint32_t*)&h1;
                    *(uint2*)(Ch + (long long)m * ldc + n) = pk;
                } else {
                    *(float4*)(Cf + (long long)m * ldc + n) =
                        make_float4(vv[0], vv[1], vv[2], vv[3]);
                }
            }
            __syncwarp();
        }
    }
}

// ---------------------------------------------------------------------------
// Fused flash attention.
//   grid (8 qblocks, 96 batch-heads), 128 threads (4 warps x 32 q rows).
//   Per iter (16 x Bc=64): S = Q@K^T, P = exp(S/8) (no max shift; scores are
//   small), O += P@V unnormalized; l[row] += rowsum(P). Final: O/l -> attnh.
// smem (bytes):
//   Q   [128][72]h   @ 0       (18432)
//   K x2[64][72]h    @ 18432   (18432)
//   V x2[64][72]h    @ 36864   (18432)
//   Sf  [4][32][68]f @ 55296   (34816)
//   Ph  [4][32][72]h @ 90112   (18432)
//   l   [128]f       @ 108544  (512)
// ---------------------------------------------------------------------------
#define FA_SMEM 109056
#define FA_OFF_K 18432
#define FA_OFF_V 36864
#define FA_OFF_SF 55296
#define FA_OFF_PH 90112
#define FA_OFF_L 108544

__global__ __launch_bounds__(128)
void flash_attn(const __half* __restrict__ qkv, __half* __restrict__ O)
{
    extern __shared__ __half smh[];
    const uint32_t sb = smem_u32(smh);
    char* smc = (char*)smh;

    const int tid = threadIdx.x;
    const int wid = tid >> 5, lid = tid & 31;
    const int qb = blockIdx.x;            // q block (128 rows)
    const int bh = blockIdx.y;            // batch*12 + head
    const int zb = bh / 12, zh = bh % 12;

    const long long TQ = 1024LL * 2304LL;
    const __half* qbase = qkv + (long long)zb * TQ + zh * 64 + (long long)(qb * 128) * 2304;
    const __half* kbase = qkv + 768  + (long long)zb * TQ + zh * 64;
    const __half* vbase = qkv + 1536 + (long long)zb * TQ + zh * 64;

    // ---- stage Q (128 rows x 128B): 1024 chunks, 8/thread ----
    #pragma unroll
    for (int q = 0; q < 8; q++) {
        const int id = q * 128 + tid;
        const int row = id >> 3, c16 = id & 7;
        cp_async16(sb + (uint32_t)(row * 144 + c16 * 16),
                   qbase + (long long)row * 2304 + c16 * 8, 16);
    }
    // ---- stage K/V iter 0 ----
    auto stageKV = [&](int it, int buf) {
        const long long r0 = (long long)(it * 64);
        const uint32_t offK = FA_OFF_K + (uint32_t)buf * 9216;
        const uint32_t offV = FA_OFF_V + (uint32_t)buf * 9216;
        #pragma unroll
        for (int q = 0; q < 4; q++) {
            const int id = q * 128 + tid;
            const int row = id >> 3, c16 = id & 7;
            const uint32_t so = (uint32_t)(row * 144 + c16 * 16);
            cp_async16(sb + offK + so, kbase + (r0 + row) * 2304 + c16 * 8, 16);
            cp_async16(sb + offV + so, vbase + (r0 + row) * 2304 + c16 * 8, 16);
        }
    };
    stageKV(0, 0);
    cp_commit();

    wmma::fragment<wmma::accumulator, 16, 16, 16, float> o_acc[2][4];
    #pragma unroll
    for (int i = 0; i < 2; i++)
        #pragma unroll
        for (int j = 0; j < 4; j++) wmma::fill_fragment(o_acc[i][j], 0.0f);
    float l = 0.0f;   // lane r owns denom of warp row r

    const __half* Qw = smh + (wid * 32) * TLDH;             // warp's Q rows
    float* Sf = (float*)(smc + FA_OFF_SF) + wid * (32 * 68);
    __half* Ph = (__half*)(smc + FA_OFF_PH) + wid * (32 * TLDH);

    for (int it = 0; it < 16; it++) {
        if (it + 1 < 16) {
            stageKV(it + 1, (it + 1) & 1);
            cp_commit();
            cp_wait<1>();
        } else {
            cp_wait<0>();
        }
        __syncthreads();

        const __half* Ks = (const __half*)(smc + FA_OFF_K + (it & 1) * 9216);
        const __half* Vs = (const __half*)(smc + FA_OFF_V + (it & 1) * 9216);

        // ---- S = Q @ K^T ----
        wmma::fragment<wmma::accumulator, 16, 16, 16, float> sa[2][4];
        #pragma unroll
        for (int i = 0; i < 2; i++)
            #pragma unroll
            for (int j = 0; j < 4; j++) wmma::fill_fragment(sa[i][j], 0.0f);
        #pragma unroll
        for (int kk = 0; kk < 4; kk++) {
            wmma::fragment<wmma::matrix_a, 16, 16, 16, __half, wmma::row_major> aq[2];
            wmma::load_matrix_sync(aq[0], Qw + kk * 16, TLDH);
            wmma::load_matrix_sync(aq[1], Qw + 16 * TLDH + kk * 16, TLDH);
            #pragma unroll
            for (int j = 0; j < 4; j++) {
                wmma::fragment<wmma::matrix_b, 16, 16, 16, __half, wmma::col_major> bk;
                wmma::load_matrix_sync(bk, Ks + (j * 16) * TLDH + kk * 16, TLDH);
                wmma::mma_sync(sa[0][j], aq[0], bk, sa[0][j]);
                wmma::mma_sync(sa[1][j], aq[1], bk, sa[1][j]);
            }
        }
        // ---- P = exp(S/8) (elementwise on fragments), store float patch ----
        #pragma unroll
        for (int i = 0; i < 2; i++)
            #pragma unroll
            for (int j = 0; j < 4; j++) {
                #pragma unroll
                for (int e = 0; e < 8; e++)
                    sa[i][j].x[e] = expf(sa[i][j].x[e] * 0.125f);
                wmma::store_matrix_sync(Sf + (i * 16) * 68 + j * 16, sa[i][j], 68,
                                        wmma::mem_row_major);
            }
        __syncwarp();
        // ---- lane pass: row sums + half conversion ----
        {
            const float* srow = Sf + lid * 68;
            __half* prow = Ph + lid * TLDH;
            float sum = 0.0f;
            #pragma unroll
            for (int c = 0; c < 64; c += 4) {
                float4 v = *(const float4*)(srow + c);
                sum += (v.x + v.y) + (v.z + v.w);
                __half2 h0 = __floats2half2_rn(v.x, v.y);
                __half2 h1 = __floats2half2_rn(v.z, v.w);
                *(__half2*)(prow + c)     = h0;
                *(__half2*)(prow + c + 2) = h1;
            }
            l += sum;
        }
        __syncwarp();
        // ---- O += P @ V ----
        #pragma unroll
        for (int kk = 0; kk < 4; kk++) {
            wmma::fragment<wmma::matrix_a, 16, 16, 16, __half, wmma::row_major> ap[2];
            wmma::load_matrix_sync(ap[0], Ph + kk * 16, TLDH);
            wmma::load_matrix_sync(ap[1], Ph + 16 * TLDH + kk * 16, TLDH);
            #pragma unroll
            for (int j = 0; j < 4; j++) {
                wmma::fragment<wmma::matrix_b, 16, 16, 16, __half, wmma::row_major> bv;
                wmma::load_matrix_sync(bv, Vs + (kk * 16) * TLDH + j * 16, TLDH);
                wmma::mma_sync(o_acc[0][j], ap[0], bv, o_acc[0][j]);
                wmma::mma_sync(o_acc[1][j], ap[1], bv, o_acc[1][j]);
            }
        }
        __syncthreads();
    }

    // ---- epilogue: O / l -> attnh ----
    float* l_sm = (float*)(smc + FA_OFF_L);
    l_sm[wid * 32 + lid] = l;
    __syncwarp();

    float* patch = Sf;   // reuse warp's Sf region (stride 16)
    const long long orow0 = (long long)zb * 1024 + qb * 128 + wid * 32;
    #pragma unroll
    for (int i = 0; i < 2; i++) {
        #pragma unroll
        for (int j = 0; j < 4; j++) {
            wmma::store_matrix_sync(patch, o_acc[i][j], 16, wmma::mem_row_major);
            __syncwarp();
            #pragma unroll
            for (int q = 0; q < 2; q++) {
                const int idx = lid + 32 * q;
                const int r = idx >> 2, c4 = idx & 3;
                float4 v = *(const float4*)(patch + r * 16 + c4 * 4);
                const float linv = 1.0f / l_sm[wid * 32 + i * 16 + r];
                __half2 h0 = __floats2half2_rn(v.x * linv, v.y * linv);
                __half2 h1 = __floats2half2_rn(v.z * linv, v.w * linv);
                uint2 pk;
                pk.x = *(uint32_t*)&h0; pk.y = *(uint32_t*)&h1;
                const long long m = orow0 + i * 16 + r;
                const int n = zh * 64 + j * 16 + c4 * 4;
                *(uint2*)(O + m * 768 + n) = pk;
            }
            __syncwarp();
        }
    }
}

// ---------------------------------------------------------------------------
// transpose float -> half:  out[c, r] = (half) in[r, c]
// ---------------------------------------------------------------------------
__global__ __launch_bounds__(256)
void transpose_f2h(const float* __restrict__ in, int ldi,
                   __half* __restrict__ out, int ldo, int R, int C)
{
    __shared__ float t[32][33];
    const int r0 = blockIdx.y * 32, c0 = blockIdx.x * 32;
    const int tx = threadIdx.x & 31, ty = threadIdx.x >> 5;
    #pragma unroll
    for (int i = 0; i < 32; i += 8) {
        const int r = r0 + ty + i, c = c0 + tx;
        t[ty + i][tx] = (r < R && c < C) ? in[(long long)r * ldi + c] : 0.f;
    }
    __syncthreads();
    #pragma unroll
    for (int i = 0; i < 32; i += 8) {
        const int r = c0 + ty + i, c = r0 + tx;
        if (r < C && c < R) out[(long long)r * ldo + c] = __float2half_rn(t[tx][ty + i]);
    }
}

__global__ __launch_bounds__(256)
void cast_f2h(const float* __restrict__ in, __half* __restrict__ out, int n)
{
    int i = blockIdx.x * 256 + threadIdx.x;
    if (i < n) out[i] = __float2half_rn(in[i]);
}

// dtw [48,1536] -> half [1536,64] transposed, K padded 48->64 with zeros
__global__ __launch_bounds__(256)
void dtw_prep(const float* __restrict__ dtw, __half* __restrict__ out)
{
    int i = blockIdx.x * 256 + threadIdx.x;
    int n = i >> 6, k = i & 63;
    out[i] = (k < 48) ? __float2half_rn(dtw[k * 1536 + n]) : __half(0.f);
}

// dbl [8192,80] -> half [8192,64], cols 48..63 zero
__global__ __launch_bounds__(256)
void dbl_prep(const float* __restrict__ dbl, __half* __restrict__ out)
{
    int i = blockIdx.x * 256 + threadIdx.x;
    int r = i >> 6, c = i & 63;
    out[i] = (c < 48) ? __float2half_rn(dbl[r * 80 + c]) : __half(0.f);
}

// ---------------------------------------------------------------------------
// LayerNorm over rows of 768, half output
// ---------------------------------------------------------------------------
__global__ __launch_bounds__(256)
void ln_kernel(const float* __restrict__ x, const float* __restrict__ g,
               const float* __restrict__ b, __half* __restrict__ y)
{
    long long row = blockIdx.x;
    const float* xr = x + row * 768;
    __half* yr = y + row * 768;
    int tid = threadIdx.x;

    float v0 = xr[tid], v1 = xr[tid + 256], v2 = xr[tid + 512];
    float s  = v0 + v1 + v2;
    float ss = v0 * v0 + v1 * v1 + v2 * v2;

    #pragma unroll
    for (int o = 16; o; o >>= 1) {
        s  += __shfl_xor_sync(0xffffffffu, s, o);
        ss += __shfl_xor_sync(0xffffffffu, ss, o);
    }
    __shared__ float sh_s[8], sh_ss[8];
    int w = tid >> 5, l = tid & 31;
    if (l == 0) { sh_s[w] = s; sh_ss[w] = ss; }
    __syncthreads();
    if (w == 0) {
        float s2  = (l < 8) ? sh_s[l]  : 0.f;
        float ss2 = (l < 8) ? sh_ss[l] : 0.f;
        #pragma unroll
        for (int o = 4; o; o >>= 1) {
            s2  += __shfl_xor_sync(0xffffffffu, s2, o);
            ss2 += __shfl_xor_sync(0xffffffffu, ss2, o);
        }
        if (l == 0) { sh_s[0] = s2; sh_ss[0] = ss2; }
    }
    __syncthreads();
    float mean = sh_s[0] * (1.0f / 768.0f);
    float var  = sh_ss[0] * (1.0f / 768.0f) - mean * mean;
    float rstd = rsqrtf(var + 1e-5f);

    yr[tid]       = __float2half_rn((v0 - mean) * rstd * g[tid]       + b[tid]);
    yr[tid + 256] = __float2half_rn((v1 - mean) * rstd * g[tid + 256] + b[tid + 256]);
    yr[tid + 512] = __float2half_rn((v2 - mean) * rstd * g[tid + 512] + b[tid + 512]);
}

// ---------------------------------------------------------------------------
// Depthwise causal conv (K=4) + bias + SiLU; float + half outputs
// ---------------------------------------------------------------------------
__global__ __launch_bounds__(256)
void conv_silu_kernel(const float* __restrict__ xz, const float* __restrict__ cw,
                      const float* __restrict__ cb, float* __restrict__ u,
                      __half* __restrict__ uh)
{
    int idx = blockIdx.x * 256 + threadIdx.x;
    int d   = idx % 1536;
    int tok = idx / 1536;
    int t   = tok & 1023;
    float acc = cb[d];
    const float* base = xz + (long long)tok * 3072 + d;
    #pragma unroll
    for (int j = 0; j < 4; j++) {
        int tt = t - 3 + j;
        if (tt >= 0) acc = fmaf(base[(long long)(j - 3) * 3072], cw[d * 4 + j], acc);
    }
    float v = silu_f(acc);
    u [(long long)tok * 1536 + d] = v;
    uh[(long long)tok * 1536 + d] = __float2half_rn(v);
}

// ---------------------------------------------------------------------------
// Selective scan: 16 lanes per (b,d) channel; fused +u*D and *silu(res)
// ---------------------------------------------------------------------------
__global__ __launch_bounds__(256)
void scan_kernel(const float* __restrict__ dt, const float* __restrict__ dbl,
                 const float* __restrict__ u, const float* __restrict__ xz,
                 const float* __restrict__ Alog, const float* __restrict__ Dp,
                 __half* __restrict__ y)
{
    int gg = blockIdx.x * 16 + (threadIdx.x >> 4);
    int s  = threadIdx.x & 15;
    int d  = gg % 1536, b = gg / 1536;

    float A  = -expf(Alog[d * 16 + s]);
    float Dv = Dp[d];
    float h  = 0.0f;
    long long tokbase = (long long)b * 1024;

    for (int t = 0; t < 1024; t++) {
        long long tok = tokbase + t;
        float dtv = dt[tok * 1536 + d];
        float uv  = u [tok * 1536 + d];
        float Bv  = dbl[tok * 80 + 48 + s];
        float Cv  = dbl[tok * 80 + 64 + s];
        float dA  = expf(dtv * A);
        h = fmaf(dA, h, dtv * Bv * uv);
        float part = h * Cv;
        part += __shfl_xor_sync(0xffffffffu, part, 8, 16);
        part += __shfl_xor_sync(0xffffffffu, part, 4, 16);
        part += __shfl_xor_sync(0xffffffffu, part, 2, 16);
        part += __shfl_xor_sync(0xffffffffu, part, 1, 16);
        if (s == 0) {
            float rv = xz[tok * 3072 + 1536 + d];
            y[tok * 1536 + d] = __float2half_rn((part + uv * Dv) * silu_f(rv));
        }
    }
}

// ---------------------------------------------------------------------------
// Host orchestration
// ---------------------------------------------------------------------------
extern "C" void kernel_launch(void* const* d_in, const int* in_sizes, int n_in,
                              void* d_out, int out_size)
{
    const float* x    = (const float*)d_in[0];
    const float* n1g  = (const float*)d_in[1];
    const float* n1b  = (const float*)d_in[2];
    const float* aiw  = (const float*)d_in[3];
    const float* aib  = (const float*)d_in[4];
    const float* aow  = (const float*)d_in[5];
    const float* aob  = (const float*)d_in[6];
    const float* n2g  = (const float*)d_in[7];
    const float* n2b  = (const float*)d_in[8];
    const float* w1   = (const float*)d_in[9];
    const float* b1   = (const float*)d_in[10];
    const float* w2   = (const float*)d_in[11];
    const float* b2   = (const float*)d_in[12];
    const float* n3g  = (const float*)d_in[13];
    const float* n3b  = (const float*)d_in[14];
    const float* minw = (const float*)d_in[15];
    const float* cw   = (const float*)d_in[16];
    const float* cb   = (const float*)d_in[17];
    const float* xpw  = (const float*)d_in[18];
    const float* dtw  = (const float*)d_in[19];
    const float* dtbi = (const float*)d_in[20];
    const float* alog = (const float*)d_in[21];
    const float* dpar = (const float*)d_in[22];
    const float* mow  = (const float*)d_in[23];
    const float* gate = (const float*)d_in[24];
    float* out = (float*)d_out;

    __half *lnh, *qkvh, *attnh, *hh, *uh, *dblh, *yh, *wth;
    float  *xz, *ub, *dbl, *gdt;
    cudaGetSymbolAddress((void**)&lnh,   g_lnh);
    cudaGetSymbolAddress((void**)&qkvh,  g_qkvh);
    cudaGetSymbolAddress((void**)&attnh, g_attnh);
    cudaGetSymbolAddress((void**)&hh,    g_hh);
    cudaGetSymbolAddress((void**)&xz,    g_xz);
    cudaGetSymbolAddress((void**)&ub,    g_u);
    cudaGetSymbolAddress((void**)&uh,    g_uh);
    cudaGetSymbolAddress((void**)&dbl,   g_dbl);
    cudaGetSymbolAddress((void**)&dblh,  g_dblh);
    cudaGetSymbolAddress((void**)&gdt,   g_dt);
    cudaGetSymbolAddress((void**)&yh,    g_yh);
    cudaGetSymbolAddress((void**)&wth,   g_wth);

    cudaFuncSetAttribute(tgemm<0, true>,  cudaFuncAttributeMaxDynamicSharedMemorySize, TG_SMEM);
    cudaFuncSetAttribute(tgemm<1, true>,  cudaFuncAttributeMaxDynamicSharedMemorySize, TG_SMEM);
    cudaFuncSetAttribute(tgemm<3, true>,  cudaFuncAttributeMaxDynamicSharedMemorySize, TG_SMEM);
    cudaFuncSetAttribute(tgemm<0, false>, cudaFuncAttributeMaxDynamicSharedMemorySize, TG_SMEM);
    cudaFuncSetAttribute(tgemm<2, false>, cudaFuncAttributeMaxDynamicSharedMemorySize, TG_SMEM);
    cudaFuncSetAttribute(tgemm<4, false>, cudaFuncAttributeMaxDynamicSharedMemorySize, TG_SMEM);
    cudaFuncSetAttribute(tgemm<5, false>, cudaFuncAttributeMaxDynamicSharedMemorySize, TG_SMEM);
    cudaFuncSetAttribute(flash_attn,      cudaFuncAttributeMaxDynamicSharedMemorySize, FA_SMEM);

    // weight preps
    cast_f2h<<<(2304 * 768 + 255) / 256, 256>>>(aiw, wth + WH_AIW, 2304 * 768);
    cast_f2h<<<(768 * 768 + 255) / 256, 256>>>(aow, wth + WH_AOW, 768 * 768);
    ln_kernel<<<8192, 256>>>(x, n1g, n1b, lnh);
    transpose_f2h<<<dim3(96, 24, 1), 256>>>(w1, 3072, wth + WH_W1, 768, 768, 3072);
    transpose_f2h<<<dim3(24, 96, 1), 256>>>(w2, 768, wth + WH_W2, 3072, 3072, 768);

    // QKV = LN1 @ attn_in_w^T + b   (M=8192, N=2304, K=768) -> half
    tgemm<1, true><<<dim3(18, 64, 1), 128, TG_SMEM>>>(
        lnh, 768, 0, 0, wth + WH_AIW, 768, 0, 0, qkvh, 2304, 0, 0,
        8192, 2304, 768, 1, aib, nullptr, 0, 1.0f, nullptr);

    transpose_f2h<<<dim3(96, 24, 1), 256>>>(minw, 3072, wth + WH_MIN, 768, 768, 3072);
    transpose_f2h<<<dim3(24, 48, 1), 256>>>(mow, 768, wth + WH_MOW, 1536, 1536, 768);
    transpose_f2h<<<dim3(3, 48, 1), 256>>>(xpw, 80, wth + WH_XPW, 1536, 1536, 80);
    dtw_prep<<<(1536 * 64 + 255) / 256, 256>>>(dtw, wth + WH_DTW);

    // fused attention: qkvh -> attnh
    flash_attn<<<dim3(8, 96), 128, FA_SMEM>>>(qkvh, attnh);

    // x = x_in + O @ attn_out_w^T + b   (float residual stream in out)
    tgemm<2, false><<<dim3(6, 64, 1), 128, TG_SMEM>>>(
        attnh, 768, 0, 0, wth + WH_AOW, 768, 0, 0, out, 768, 0, 0,
        8192, 768, 768, 1, aob, x, 768, 1.0f, nullptr);

    // LN2
    ln_kernel<<<8192, 256>>>(out, n2g, n2b, lnh);

    // H = gelu(LN2 @ W1 + b1)   (N=3072) -> half
    tgemm<3, true><<<dim3(24, 64, 1), 128, TG_SMEM>>>(
        lnh, 768, 0, 0, wth + WH_W1, 768, 0, 0, hh, 3072, 0, 0,
        8192, 3072, 768, 1, b1, nullptr, 0, 1.0f, nullptr);

    // x += H @ W2 + b2
    tgemm<2, false><<<dim3(6, 64, 1), 128, TG_SMEM>>>(
        hh, 3072, 0, 0, wth + WH_W2, 3072, 0, 0, out, 768, 0, 0,
        8192, 768, 3072, 1, b2, out, 768, 1.0f, nullptr);

    // LN3
    ln_kernel<<<8192, 256>>>(out, n3g, n3b, lnh);

    // xz = LN3 @ m_in_w   (N=3072) -> float
    tgemm<0, false><<<dim3(24, 64, 1), 128, TG_SMEM>>>(
        lnh, 768, 0, 0, wth + WH_MIN, 768, 0, 0, xz, 3072, 0, 0,
        8192, 3072, 768, 1, nullptr, nullptr, 0, 1.0f, nullptr);

    // u = silu(conv(xz[:, :1536]) + cb) -> float + half
    conv_silu_kernel<<<49152, 256>>>(xz, cw, cb, ub, uh);

    // dbl = u @ xproj_w   (N=80, K=1536) -> float
    tgemm<0, false><<<dim3(1, 64, 1), 128, TG_SMEM>>>(
        uh, 1536, 0, 0, wth + WH_XPW, 1536, 0, 0, dbl, 80, 0, 0,
        8192, 80, 1536, 1, nullptr, nullptr, 0, 1.0f, nullptr);

    // dbl[:, :48] -> half padded [8192,64]
    dbl_prep<<<(8192 * 64 + 255) / 256, 256>>>(dbl, dblh);

    // dt = softplus(dbl48 @ dt_w + dt_b)   (N=1536, K=64 padded) -> float
    tgemm<4, false><<<dim3(12, 64, 1), 128, TG_SMEM>>>(
        dblh, 64, 0, 0, wth + WH_DTW, 64, 0, 0, gdt, 1536, 0, 0,
        8192, 1536, 64, 1, dtbi, nullptr, 0, 1.0f, nullptr);

    // selective scan + (u*D) + *silu(res) -> half
    scan_kernel<<<768, 256>>>(gdt, dbl, ub, xz, alog, dpar, yh);

    // out = x + sigmoid(gate) * (y @ m_out_w)   (K=1536)
    tgemm<5, false><<<dim3(6, 64, 1), 128, TG_SMEM>>>(
        yh, 1536, 0, 0, wth + WH_MOW, 1536, 0, 0, out, 768, 0, 0,
        8192, 768, 1536, 1, nullptr, out, 768, 1.0f, gate);
}